// round 1
// baseline (speedup 1.0000x reference)
#include <cuda_runtime.h>
#include <cstdint>

#define QLENC 1024
#define BSZC  4
#define NHC   16
#define DHC   64
#define DMC   1024
#define H3C   3072
#define ROWSC 4096   // QLEN*BSZ
#define CONVC 7
#define SCALEC 0.125f
#define NEGC  -1e30f

// ---------------- scratch (no allocation allowed) ----------------
__device__ float g_heads[(size_t)ROWSC * H3C];   // [row=q*4+b][3*N*D]
__device__ float g_qh[(size_t)ROWSC * DMC];      // [l][b][n][d]
__device__ float g_kh[(size_t)ROWSC * DMC];
__device__ float g_vh[(size_t)ROWSC * DMC];
__device__ float g_rk[(size_t)QLENC * DMC];      // [rho][n][d]
__device__ float g_attv[(size_t)ROWSC * DMC];    // [row][n*64+d]
__device__ float g_aout[(size_t)ROWSC * DMC];

// ---------------- SGEMM: C[M,N] = A[M,K] * B[N,K]^T (both row-major) ------
__global__ __launch_bounds__(256, 2)
void sgemm_tn(const float* __restrict__ A, const float* __restrict__ B,
              float* __restrict__ C, int M, int N, int K)
{
    __shared__ float As[2][16][128];
    __shared__ float Bs[2][16][128];
    const int t  = threadIdx.x;
    const int tx = t & 15, ty = t >> 4;
    const int m0 = blockIdx.y << 7, n0 = blockIdx.x << 7;
    const int lr = t >> 1;            // 0..127 : tile row loaded by this thread
    const int lk = (t & 1) << 3;      // 0 or 8 : k offset

    const float* Ap = A + (size_t)(m0 + lr) * K + lk;
    const float* Bp = B + (size_t)(n0 + lr) * K + lk;

    float4 a0 = *(const float4*)(Ap);
    float4 a1 = *(const float4*)(Ap + 4);
    float4 b0 = *(const float4*)(Bp);
    float4 b1 = *(const float4*)(Bp + 4);

    float acc[8][8];
#pragma unroll
    for (int i = 0; i < 8; i++)
#pragma unroll
        for (int j = 0; j < 8; j++) acc[i][j] = 0.f;

    As[0][lk+0][lr] = a0.x; As[0][lk+1][lr] = a0.y;
    As[0][lk+2][lr] = a0.z; As[0][lk+3][lr] = a0.w;
    As[0][lk+4][lr] = a1.x; As[0][lk+5][lr] = a1.y;
    As[0][lk+6][lr] = a1.z; As[0][lk+7][lr] = a1.w;
    Bs[0][lk+0][lr] = b0.x; Bs[0][lk+1][lr] = b0.y;
    Bs[0][lk+2][lr] = b0.z; Bs[0][lk+3][lr] = b0.w;
    Bs[0][lk+4][lr] = b1.x; Bs[0][lk+5][lr] = b1.y;
    Bs[0][lk+6][lr] = b1.z; Bs[0][lk+7][lr] = b1.w;
    __syncthreads();

    const int nk = K >> 4;
    for (int kt = 0; kt < nk; kt++) {
        const int cur = kt & 1;
        if (kt + 1 < nk) {
            const float* Ap2 = Ap + ((kt + 1) << 4);
            const float* Bp2 = Bp + ((kt + 1) << 4);
            a0 = *(const float4*)(Ap2);
            a1 = *(const float4*)(Ap2 + 4);
            b0 = *(const float4*)(Bp2);
            b1 = *(const float4*)(Bp2 + 4);
        }
#pragma unroll
        for (int kk = 0; kk < 16; kk++) {
            float4 x0 = *(const float4*)&As[cur][kk][ty << 3];
            float4 x1 = *(const float4*)&As[cur][kk][(ty << 3) + 4];
            float4 y0 = *(const float4*)&Bs[cur][kk][tx << 3];
            float4 y1 = *(const float4*)&Bs[cur][kk][(tx << 3) + 4];
            float av[8] = {x0.x, x0.y, x0.z, x0.w, x1.x, x1.y, x1.z, x1.w};
            float bv[8] = {y0.x, y0.y, y0.z, y0.w, y1.x, y1.y, y1.z, y1.w};
#pragma unroll
            for (int i = 0; i < 8; i++)
#pragma unroll
                for (int j = 0; j < 8; j++)
                    acc[i][j] = fmaf(av[i], bv[j], acc[i][j]);
        }
        if (kt + 1 < nk) {
            const int nx = (kt + 1) & 1;
            As[nx][lk+0][lr] = a0.x; As[nx][lk+1][lr] = a0.y;
            As[nx][lk+2][lr] = a0.z; As[nx][lk+3][lr] = a0.w;
            As[nx][lk+4][lr] = a1.x; As[nx][lk+5][lr] = a1.y;
            As[nx][lk+6][lr] = a1.z; As[nx][lk+7][lr] = a1.w;
            Bs[nx][lk+0][lr] = b0.x; Bs[nx][lk+1][lr] = b0.y;
            Bs[nx][lk+2][lr] = b0.z; Bs[nx][lk+3][lr] = b0.w;
            Bs[nx][lk+4][lr] = b1.x; Bs[nx][lk+5][lr] = b1.y;
            Bs[nx][lk+6][lr] = b1.z; Bs[nx][lk+7][lr] = b1.w;
            __syncthreads();
        }
    }
#pragma unroll
    for (int i = 0; i < 8; i++) {
        float* Cp = C + (size_t)(m0 + (ty << 3) + i) * N + n0 + (tx << 3);
        *(float4*)(Cp)     = make_float4(acc[i][0], acc[i][1], acc[i][2], acc[i][3]);
        *(float4*)(Cp + 4) = make_float4(acc[i][4], acc[i][5], acc[i][6], acc[i][7]);
    }
}

// ---------------- depthwise-style conv1d over L, full channel mix ----------
// x[(n,b)][i][l] read straight out of g_heads; y -> [l][b][n][o]
__global__ __launch_bounds__(256)
void conv_head(const float* __restrict__ heads, int colbase,
               const float* __restrict__ cw, const float* __restrict__ cb,
               float* __restrict__ out)
{
    __shared__ float xs[DHC][134];      // 128 L-tile + 6 halo
    const int nb = blockIdx.x;          // n*4 + b
    const int n  = nb >> 2, b = nb & 3;
    const int l0 = blockIdx.y << 7;
    const int t  = threadIdx.x;

    for (int u = t; u < DHC * 134; u += 256) {
        const int ll = u >> 6;
        const int i  = u & 63;
        const int gl = l0 + ll - 3;
        float v = 0.f;
        if (gl >= 0 && gl < QLENC)
            v = heads[(size_t)(gl * BSZC + b) * H3C + colbase + n * DHC + i];
        xs[i][ll] = v;
    }
    __syncthreads();

    const int o  = t & 63;
    const int lb = (t >> 6) << 5;       // 4 groups * 32 contiguous l
    float acc[32];
    const float bias = cb[o];
#pragma unroll
    for (int l = 0; l < 32; l++) acc[l] = bias;

    for (int i = 0; i < DHC; i++) {
        float xr[38];
#pragma unroll
        for (int q = 0; q < 38; q++) xr[q] = xs[i][lb + q];
        const float* wp = cw + (o * DHC + i) * CONVC;
#pragma unroll
        for (int k = 0; k < CONVC; k++) {
            const float wv = __ldg(wp + k);
#pragma unroll
            for (int l = 0; l < 32; l++) acc[l] = fmaf(wv, xr[l + k], acc[l]);
        }
    }
#pragma unroll
    for (int l = 0; l < 32; l++) {
        const int gl = l0 + lb + l;
        out[(size_t)((gl * BSZC + b) * NHC + n) * DHC + o] = acc[l];
    }
}

// ---------------- fused rel-attention (flash-style, rel_shift folded) ------
// score[i,j] = (q_i+rwb)·k_j + (q_i+rrb)·rk[klen-1-(i-j)]   (j<=i)
#define SMEM_ATT ((5 * 64 * 68 + 64 * 128) * 4)

__global__ __launch_bounds__(256)
void attn_kernel(const float* __restrict__ qh, const float* __restrict__ kh,
                 const float* __restrict__ vh, const float* __restrict__ rk,
                 const float* __restrict__ rwb, const float* __restrict__ rrb,
                 float* __restrict__ attv)
{
    extern __shared__ float smbuf[];
    float* qw  = smbuf;            // [d][i]  stride 68
    float* qr  = qw + 64 * 68;     // [d][i]
    float* ks  = qr + 64 * 68;     // [d][j]
    float* vs  = ks + 64 * 68;     // [j][d]
    float* ps  = vs + 64 * 68;     // [j][i]
    float* rks = ps + 64 * 68;     // [d][x]  stride 128, x = drel - dmin

    const int i0 = blockIdx.x << 6;
    const int b  = blockIdx.y, n = blockIdx.z;
    const int t  = threadIdx.x, tx = t & 15, ty = t >> 4;

    for (int u = t; u < 64 * 64; u += 256) {
        const int il = u >> 6, d = u & 63;
        const float v = qh[(size_t)(((i0 + il) * BSZC + b) * NHC + n) * DHC + d];
        qw[d * 68 + il] = v + rwb[n * DHC + d];
        qr[d * 68 + il] = v + rrb[n * DHC + d];
    }

    float m_r[4], l_r[4], oacc[4][4];
#pragma unroll
    for (int a = 0; a < 4; a++) {
        m_r[a] = -1e30f; l_r[a] = 0.f;
#pragma unroll
        for (int c = 0; c < 4; c++) oacc[a][c] = 0.f;
    }

    const int cb_ = 63 + 4 * (ty - tx);   // window center index into rks x-dim

    for (int j0 = 0; j0 <= i0; j0 += 64) {
        __syncthreads();
        for (int u = t; u < 64 * 64; u += 256) {
            const int jl = u >> 6, d = u & 63;
            const size_t g = (size_t)(((j0 + jl) * BSZC + b) * NHC + n) * DHC + d;
            ks[d * 68 + jl] = kh[g];
            vs[jl * 68 + d] = vh[g];
        }
        const int dbase = i0 - j0 - 63;   // dmin
        for (int u = t; u < 64 * 127; u += 256) {
            const int d = u / 127, x = u % 127;
            const int drel = dbase + x;
            float v = 0.f;
            if (drel >= 0)
                v = rk[(size_t)((QLENC - 1 - drel) * NHC + n) * DHC + d];
            rks[d * 128 + x] = v;
        }
        __syncthreads();

        float s[4][4];
#pragma unroll
        for (int a = 0; a < 4; a++)
#pragma unroll
            for (int c = 0; c < 4; c++) s[a][c] = 0.f;

#pragma unroll 4
        for (int d = 0; d < 64; d++) {
            float4 x0 = *(const float4*)&qw[d * 68 + (ty << 2)];
            float4 x1 = *(const float4*)&qr[d * 68 + (ty << 2)];
            float4 y0 = *(const float4*)&ks[d * 68 + (tx << 2)];
            float4 r0 = *(const float4*)&rks[d * 128 + cb_ - 3];
            float4 r1 = *(const float4*)&rks[d * 128 + cb_ + 1];
            float aw[4] = {x0.x, x0.y, x0.z, x0.w};
            float ar[4] = {x1.x, x1.y, x1.z, x1.w};
            float kv[4] = {y0.x, y0.y, y0.z, y0.w};
            float rr[8] = {r0.x, r0.y, r0.z, r0.w, r1.x, r1.y, r1.z, r1.w};
#pragma unroll
            for (int a = 0; a < 4; a++)
#pragma unroll
                for (int c = 0; c < 4; c++)
                    s[a][c] = fmaf(aw[a], kv[c], fmaf(ar[a], rr[3 + a - c], s[a][c]));
        }

        // scale + causal mask + online softmax (row group = half warp)
#pragma unroll
        for (int a = 0; a < 4; a++) {
            const int gi = i0 + (ty << 2) + a;
            float mx = -1e30f;
#pragma unroll
            for (int c = 0; c < 4; c++) {
                const int gj = j0 + (tx << 2) + c;
                float v = s[a][c] * SCALEC;
                if (gj > gi) v = NEGC;
                s[a][c] = v;
                mx = fmaxf(mx, v);
            }
#pragma unroll
            for (int off = 1; off < 16; off <<= 1)
                mx = fmaxf(mx, __shfl_xor_sync(0xffffffffu, mx, off, 16));
            const float mnew = fmaxf(m_r[a], mx);
            const float corr = __expf(m_r[a] - mnew);
            float psum = 0.f;
#pragma unroll
            for (int c = 0; c < 4; c++) {
                const float p = __expf(s[a][c] - mnew);
                s[a][c] = p;
                psum += p;
            }
#pragma unroll
            for (int off = 1; off < 16; off <<= 1)
                psum += __shfl_xor_sync(0xffffffffu, psum, off, 16);
            l_r[a] = l_r[a] * corr + psum;
            m_r[a] = mnew;
#pragma unroll
            for (int c = 0; c < 4; c++) oacc[a][c] *= corr;
        }
        // p -> shared, transposed to [j][i]
#pragma unroll
        for (int c = 0; c < 4; c++) {
            *(float4*)&ps[((tx << 2) + c) * 68 + (ty << 2)] =
                make_float4(s[0][c], s[1][c], s[2][c], s[3][c]);
        }
        __syncthreads();
        // PV accumulate: o[i][dd] += p[i][j] * v[j][dd]
#pragma unroll 8
        for (int j = 0; j < 64; j++) {
            float4 p4 = *(const float4*)&ps[j * 68 + (ty << 2)];
            float4 v4 = *(const float4*)&vs[j * 68 + (tx << 2)];
            float pv[4] = {p4.x, p4.y, p4.z, p4.w};
            float vv[4] = {v4.x, v4.y, v4.z, v4.w};
#pragma unroll
            for (int a = 0; a < 4; a++)
#pragma unroll
                for (int c = 0; c < 4; c++)
                    oacc[a][c] = fmaf(pv[a], vv[c], oacc[a][c]);
        }
    }
#pragma unroll
    for (int a = 0; a < 4; a++) {
        const float inv = 1.f / l_r[a];
        float* op = attv +
            (size_t)(((i0 + (ty << 2) + a) * BSZC + b) * NHC + n) * DHC + (tx << 2);
        *(float4*)op = make_float4(oacc[a][0] * inv, oacc[a][1] * inv,
                                   oacc[a][2] * inv, oacc[a][3] * inv);
    }
}

// ---------------- residual + LayerNorm ----------------
__global__ __launch_bounds__(256)
void ln_kernel(const float* __restrict__ w, const float* __restrict__ ao,
               const float* __restrict__ gamma, const float* __restrict__ beta,
               float* __restrict__ out)
{
    __shared__ float red[16];
    const int row = blockIdx.x, t = threadIdx.x;
    const size_t base = (size_t)row * DMC + t * 4;
    const float4 wv = *(const float4*)(w + base);
    const float4 av = *(const float4*)(ao + base);
    float x[4] = {wv.x + av.x, wv.y + av.y, wv.z + av.z, wv.w + av.w};
    float s1 = x[0] + x[1] + x[2] + x[3];
    float s2 = x[0]*x[0] + x[1]*x[1] + x[2]*x[2] + x[3]*x[3];
#pragma unroll
    for (int off = 16; off; off >>= 1) {
        s1 += __shfl_xor_sync(0xffffffffu, s1, off);
        s2 += __shfl_xor_sync(0xffffffffu, s2, off);
    }
    if ((t & 31) == 0) { red[t >> 5] = s1; red[8 + (t >> 5)] = s2; }
    __syncthreads();
    float ts1 = 0.f, ts2 = 0.f;
#pragma unroll
    for (int i = 0; i < 8; i++) { ts1 += red[i]; ts2 += red[8 + i]; }
    const float mu   = ts1 * (1.f / DMC);
    const float var  = ts2 * (1.f / DMC) - mu * mu;
    const float rstd = rsqrtf(var + 1e-5f);
    const float4 gv = *(const float4*)(gamma + t * 4);
    const float4 bv = *(const float4*)(beta + t * 4);
    float4 o;
    o.x = (x[0] - mu) * rstd * gv.x + bv.x;
    o.y = (x[1] - mu) * rstd * gv.y + bv.y;
    o.z = (x[2] - mu) * rstd * gv.z + bv.z;
    o.w = (x[3] - mu) * rstd * gv.w + bv.w;
    *(float4*)(out + base) = o;
}

// ---------------- launcher ----------------
extern "C" void kernel_launch(void* const* d_in, const int* in_sizes, int n_in,
                              void* d_out, int out_size)
{
    (void)in_sizes; (void)n_in; (void)out_size;
    const float* w    = (const float*)d_in[0];
    const float* r    = (const float*)d_in[1];
    const float* rwb  = (const float*)d_in[2];
    const float* rrb  = (const float*)d_in[3];
    const float* Wqkv = (const float*)d_in[4];
    const float* Wr   = (const float*)d_in[5];
    const float* Wo   = (const float*)d_in[6];
    const float* cwq  = (const float*)d_in[7];
    const float* cbq  = (const float*)d_in[8];
    const float* cwk  = (const float*)d_in[9];
    const float* cbk  = (const float*)d_in[10];
    const float* cwv  = (const float*)d_in[11];
    const float* cbv  = (const float*)d_in[12];
    const float* gam  = (const float*)d_in[13];
    const float* bet  = (const float*)d_in[14];
    // d_in[15] = causal mask, structurally known -> ignored

    float *heads, *qh, *kh, *vh, *rkb, *attv, *aout;
    cudaGetSymbolAddress((void**)&heads, g_heads);
    cudaGetSymbolAddress((void**)&qh,    g_qh);
    cudaGetSymbolAddress((void**)&kh,    g_kh);
    cudaGetSymbolAddress((void**)&vh,    g_vh);
    cudaGetSymbolAddress((void**)&rkb,   g_rk);
    cudaGetSymbolAddress((void**)&attv,  g_attv);
    cudaGetSymbolAddress((void**)&aout,  g_aout);

    cudaFuncSetAttribute(attn_kernel,
                         cudaFuncAttributeMaxDynamicSharedMemorySize, SMEM_ATT);

    // 1. heads = w @ W_qkv^T   [4096 x 3072]
    sgemm_tn<<<dim3(H3C / 128, ROWSC / 128), 256>>>(w, Wqkv, heads, ROWSC, H3C, DMC);
    // 2. r_head_k = r @ W_r^T  [1024 x 1024]
    sgemm_tn<<<dim3(DMC / 128, QLENC / 128), 256>>>(r, Wr, rkb, QLENC, DMC, DMC);
    // 3. convs
    conv_head<<<dim3(64, 8), 256>>>(heads, 0,       cwq, cbq, qh);
    conv_head<<<dim3(64, 8), 256>>>(heads, DMC,     cwk, cbk, kh);
    conv_head<<<dim3(64, 8), 256>>>(heads, 2 * DMC, cwv, cbv, vh);
    // 4. fused rel-attention
    attn_kernel<<<dim3(16, 4, 16), 256, SMEM_ATT>>>(qh, kh, vh, rkb, rwb, rrb, attv);
    // 5. out projection
    sgemm_tn<<<dim3(DMC / 128, ROWSC / 128), 256>>>(attv, Wo, aout, ROWSC, DMC, DMC);
    // 6. residual + LN
    ln_kernel<<<ROWSC, 256>>>(w, aout, gam, bet, (float*)d_out);
}

// round 2
// speedup vs baseline: 1.6961x; 1.6961x over previous
#include <cuda_runtime.h>
#include <cstdint>

#define QLENC 1024
#define BSZC  4
#define NHC   16
#define DHC   64
#define DMC   1024
#define H3C   3072
#define ROWSC 4096   // QLEN*BSZ
#define CONVC 7
#define SCALEC 0.125f
#define NEGC  -1e30f

// ---------------- scratch (no allocation allowed) ----------------
__device__ float g_heads[(size_t)ROWSC * H3C];   // [row=q*4+b][3*N*D]
__device__ float g_qh[(size_t)ROWSC * DMC];      // [l][b][n][d]
__device__ float g_kh[(size_t)ROWSC * DMC];
__device__ float g_vh[(size_t)ROWSC * DMC];
__device__ float g_rk[(size_t)QLENC * DMC];      // [rho][n][d]
__device__ float g_attv[(size_t)ROWSC * DMC];    // [row][n*64+d]
__device__ float g_aout[(size_t)ROWSC * DMC];
__device__ uint32_t g_wtq[448 * 64];             // conv weights, [k*64+i][o], tf32 bits
__device__ uint32_t g_wtk[448 * 64];
__device__ uint32_t g_wtv[448 * 64];

// ---------------- tf32 helpers ----------------
__device__ __forceinline__ uint32_t f2tf(float x) {
    uint32_t r;
    asm("cvt.rna.tf32.f32 %0, %1;" : "=r"(r) : "f"(x));
    return r;
}

__device__ __forceinline__ void mma_tf32(float c[4], const uint32_t a[4],
                                         const uint32_t b[2]) {
    asm volatile(
        "mma.sync.aligned.m16n8k8.row.col.f32.tf32.tf32.f32 "
        "{%0,%1,%2,%3}, {%4,%5,%6,%7}, {%8,%9}, {%0,%1,%2,%3};"
        : "+f"(c[0]), "+f"(c[1]), "+f"(c[2]), "+f"(c[3])
        : "r"(a[0]), "r"(a[1]), "r"(a[2]), "r"(a[3]), "r"(b[0]), "r"(b[1]));
}

// ---------------- TF32 SGEMM: C[M,N] = A[M,K] * B[N,K]^T ----------------
// Block 128x128, warp 64x32, k-chunk 16, double-buffered smem.
__global__ __launch_bounds__(256)
void sgemm_tf32(const float* __restrict__ A, const float* __restrict__ B,
                float* __restrict__ C, int M, int N, int K)
{
    __shared__ uint32_t As[2][16][136];
    __shared__ uint32_t Bs[2][16][136];
    const int t = threadIdx.x;
    const int warp = t >> 5, lane = t & 31;
    const int wm = (warp >> 2) * 64, wn = (warp & 3) * 32;
    const int r = lane >> 2, c = lane & 3;
    const int m0 = blockIdx.y << 7, n0 = blockIdx.x << 7;
    const int lr = t & 127;
    const int lk = (t >> 7) << 3;       // 0 or 8

    const float* Ap = A + (size_t)(m0 + lr) * K + lk;
    const float* Bp = B + (size_t)(n0 + lr) * K + lk;

    float acc[4][4][4];
#pragma unroll
    for (int mf = 0; mf < 4; mf++)
#pragma unroll
        for (int nf = 0; nf < 4; nf++)
#pragma unroll
            for (int q = 0; q < 4; q++) acc[mf][nf][q] = 0.f;

    float4 pa0 = *(const float4*)(Ap);
    float4 pa1 = *(const float4*)(Ap + 4);
    float4 pb0 = *(const float4*)(Bp);
    float4 pb1 = *(const float4*)(Bp + 4);

    {
        float av[8] = {pa0.x, pa0.y, pa0.z, pa0.w, pa1.x, pa1.y, pa1.z, pa1.w};
        float bv[8] = {pb0.x, pb0.y, pb0.z, pb0.w, pb1.x, pb1.y, pb1.z, pb1.w};
#pragma unroll
        for (int q = 0; q < 8; q++) {
            As[0][lk + q][lr] = f2tf(av[q]);
            Bs[0][lk + q][lr] = f2tf(bv[q]);
        }
    }
    __syncthreads();

    const int nk = K >> 4;
    for (int kt = 0; kt < nk; kt++) {
        const int cur = kt & 1;
        if (kt + 1 < nk) {
            const float* Ap2 = Ap + ((kt + 1) << 4);
            const float* Bp2 = Bp + ((kt + 1) << 4);
            pa0 = *(const float4*)(Ap2);
            pa1 = *(const float4*)(Ap2 + 4);
            pb0 = *(const float4*)(Bp2);
            pb1 = *(const float4*)(Bp2 + 4);
        }
#pragma unroll
        for (int ks = 0; ks < 2; ks++) {
            const int kb = ks << 3;
            uint32_t af[4][4];
#pragma unroll
            for (int mf = 0; mf < 4; mf++) {
                const int m = wm + mf * 16 + r;
                af[mf][0] = As[cur][kb + c][m];
                af[mf][1] = As[cur][kb + c][m + 8];
                af[mf][2] = As[cur][kb + c + 4][m];
                af[mf][3] = As[cur][kb + c + 4][m + 8];
            }
            uint32_t bf[4][2];
#pragma unroll
            for (int nf = 0; nf < 4; nf++) {
                const int n = wn + nf * 8 + r;
                bf[nf][0] = Bs[cur][kb + c][n];
                bf[nf][1] = Bs[cur][kb + c + 4][n];
            }
#pragma unroll
            for (int mf = 0; mf < 4; mf++)
#pragma unroll
                for (int nf = 0; nf < 4; nf++)
                    mma_tf32(acc[mf][nf], af[mf], bf[nf]);
        }
        if (kt + 1 < nk) {
            const int nx = (kt + 1) & 1;
            float av[8] = {pa0.x, pa0.y, pa0.z, pa0.w, pa1.x, pa1.y, pa1.z, pa1.w};
            float bv[8] = {pb0.x, pb0.y, pb0.z, pb0.w, pb1.x, pb1.y, pb1.z, pb1.w};
#pragma unroll
            for (int q = 0; q < 8; q++) {
                As[nx][lk + q][lr] = f2tf(av[q]);
                Bs[nx][lk + q][lr] = f2tf(bv[q]);
            }
            __syncthreads();
        }
    }

#pragma unroll
    for (int mf = 0; mf < 4; mf++) {
#pragma unroll
        for (int nf = 0; nf < 4; nf++) {
            const int row = m0 + wm + mf * 16 + r;
            const int col = n0 + wn + nf * 8 + (c << 1);
            float2* p0 = (float2*)(C + (size_t)row * N + col);
            float2* p1 = (float2*)(C + (size_t)(row + 8) * N + col);
            *p0 = make_float2(acc[mf][nf][0], acc[mf][nf][1]);
            *p1 = make_float2(acc[mf][nf][2], acc[mf][nf][3]);
        }
    }
}

// ---------------- conv weight transform: cw[O][I][K] -> wt[k*64+i][o] tf32 ---
__global__ void wt_xform(const float* __restrict__ cw, uint32_t* __restrict__ wt)
{
    const int idx = blockIdx.x * 256 + threadIdx.x;
    if (idx >= 448 * 64) return;
    const int kidx = idx >> 6, o = idx & 63;
    const int i = kidx & 63, k = kidx >> 6;
    wt[idx] = f2tf(cw[(o * 64 + i) * CONVC + k]);
}

// ---------------- conv1d as shifted GEMM on tensor cores -------------------
// y[l][o] = sum_{i,k} x[l+k-3][i] * cw[o][i][k], per (n,b).
// Block: 128 l-tile x 64 o. K = 448 in chunks of 32 (fixed shift per chunk).
__global__ __launch_bounds__(256)
void conv_mma(const float* __restrict__ heads, int colbase,
              const uint32_t* __restrict__ wt, const float* __restrict__ cb,
              float* __restrict__ out)
{
    __shared__ uint32_t xs[134][68];   // [l - l0 + 3][i], tf32 bits
    __shared__ uint32_t bs[32][72];    // [ii][o]
    const int t = threadIdx.x;
    const int warp = t >> 5, lane = t & 31;
    const int wm = (warp >> 1) * 32, wn = (warp & 1) * 32;
    const int r = lane >> 2, c = lane & 3;
    const int nb = blockIdx.y;
    const int n = nb >> 2, b = nb & 3;
    const int l0 = blockIdx.x << 7;

    // fill x tile (with halo, zero-padded)
    for (int u = t; u < 134 * 16; u += 256) {
        const int row = u >> 4, i4 = (u & 15) << 2;
        const int gl = l0 + row - 3;
        float4 v = make_float4(0.f, 0.f, 0.f, 0.f);
        if (gl >= 0 && gl < QLENC)
            v = *(const float4*)(heads + (size_t)(gl * BSZC + b) * H3C +
                                 colbase + n * DHC + i4);
        xs[row][i4]     = f2tf(v.x);
        xs[row][i4 + 1] = f2tf(v.y);
        xs[row][i4 + 2] = f2tf(v.z);
        xs[row][i4 + 3] = f2tf(v.w);
    }

    float acc[2][4][4];
#pragma unroll
    for (int mf = 0; mf < 2; mf++)
#pragma unroll
        for (int nf = 0; nf < 4; nf++)
#pragma unroll
            for (int q = 0; q < 4; q++) acc[mf][nf][q] = 0.f;

    for (int chunk = 0; chunk < 14; chunk++) {
        const int k = chunk >> 1;
        const int ibase = (chunk & 1) << 5;
        __syncthreads();   // protect xs (first iter) / bs reuse
        // fill bs[ii][o] = wt[(k*64 + ibase + ii)*64 + o]  (already tf32)
        for (int u = t; u < 32 * 16; u += 256) {
            const int ii = u >> 4, o4 = (u & 15) << 2;
            *(uint4*)&bs[ii][o4] =
                *(const uint4*)(wt + ((size_t)(k * 64 + ibase + ii) << 6) + o4);
        }
        __syncthreads();

#pragma unroll
        for (int ks = 0; ks < 4; ks++) {
            const int kb = ks << 3;
            uint32_t af[2][4];
#pragma unroll
            for (int mf = 0; mf < 2; mf++) {
                const int m = wm + mf * 16 + r;
                af[mf][0] = xs[m + k][ibase + kb + c];
                af[mf][1] = xs[m + 8 + k][ibase + kb + c];
                af[mf][2] = xs[m + k][ibase + kb + c + 4];
                af[mf][3] = xs[m + 8 + k][ibase + kb + c + 4];
            }
            uint32_t bf[4][2];
#pragma unroll
            for (int nf = 0; nf < 4; nf++) {
                const int o = wn + nf * 8 + r;
                bf[nf][0] = bs[kb + c][o];
                bf[nf][1] = bs[kb + c + 4][o];
            }
#pragma unroll
            for (int mf = 0; mf < 2; mf++)
#pragma unroll
                for (int nf = 0; nf < 4; nf++)
                    mma_tf32(acc[mf][nf], af[mf], bf[nf]);
        }
    }

#pragma unroll
    for (int mf = 0; mf < 2; mf++) {
#pragma unroll
        for (int nf = 0; nf < 4; nf++) {
            const int gl = l0 + wm + mf * 16 + r;
            const int o = wn + nf * 8 + (c << 1);
            const float b0 = __ldg(cb + o), b1 = __ldg(cb + o + 1);
            float2* p0 = (float2*)(out + (size_t)((gl * BSZC + b) * NHC + n) * DHC + o);
            float2* p1 = (float2*)(out + (size_t)(((gl + 8) * BSZC + b) * NHC + n) * DHC + o);
            *p0 = make_float2(acc[mf][nf][0] + b0, acc[mf][nf][1] + b1);
            *p1 = make_float2(acc[mf][nf][2] + b0, acc[mf][nf][3] + b1);
        }
    }
}

// ---------------- fused rel-attention (flash-style, rel_shift folded) ------
// score[i,j] = (q_i+rwb)·k_j + (q_i+rrb)·rk[klen-1-(i-j)]   (j<=i)
#define SMEM_ATT ((5 * 64 * 68 + 64 * 128) * 4)

__global__ __launch_bounds__(256)
void attn_kernel(const float* __restrict__ qh, const float* __restrict__ kh,
                 const float* __restrict__ vh, const float* __restrict__ rk,
                 const float* __restrict__ rwb, const float* __restrict__ rrb,
                 float* __restrict__ attv)
{
    extern __shared__ float smbuf[];
    float* qw  = smbuf;            // [d][i]  stride 68
    float* qr  = qw + 64 * 68;     // [d][i]
    float* ks  = qr + 64 * 68;     // [d][j]
    float* vs  = ks + 64 * 68;     // [j][d]
    float* ps  = vs + 64 * 68;     // [j][i]
    float* rks = ps + 64 * 68;     // [d][x]  stride 128, x = drel - dmin

    const int i0 = blockIdx.x << 6;
    const int b  = blockIdx.y, n = blockIdx.z;
    const int t  = threadIdx.x, tx = t & 15, ty = t >> 4;

    for (int u = t; u < 64 * 64; u += 256) {
        const int il = u >> 6, d = u & 63;
        const float v = qh[(size_t)(((i0 + il) * BSZC + b) * NHC + n) * DHC + d];
        qw[d * 68 + il] = v + rwb[n * DHC + d];
        qr[d * 68 + il] = v + rrb[n * DHC + d];
    }

    float m_r[4], l_r[4], oacc[4][4];
#pragma unroll
    for (int a = 0; a < 4; a++) {
        m_r[a] = -1e30f; l_r[a] = 0.f;
#pragma unroll
        for (int c = 0; c < 4; c++) oacc[a][c] = 0.f;
    }

    const int cb_ = 63 + 4 * (ty - tx);   // window center index into rks x-dim

    for (int j0 = 0; j0 <= i0; j0 += 64) {
        __syncthreads();
        for (int u = t; u < 64 * 64; u += 256) {
            const int jl = u >> 6, d = u & 63;
            const size_t g = (size_t)(((j0 + jl) * BSZC + b) * NHC + n) * DHC + d;
            ks[d * 68 + jl] = kh[g];
            vs[jl * 68 + d] = vh[g];
        }
        const int dbase = i0 - j0 - 63;   // dmin
        for (int u = t; u < 64 * 127; u += 256) {
            const int d = u / 127, x = u % 127;
            const int drel = dbase + x;
            float v = 0.f;
            if (drel >= 0)
                v = rk[(size_t)((QLENC - 1 - drel) * NHC + n) * DHC + d];
            rks[d * 128 + x] = v;
        }
        __syncthreads();

        float s[4][4];
#pragma unroll
        for (int a = 0; a < 4; a++)
#pragma unroll
            for (int c = 0; c < 4; c++) s[a][c] = 0.f;

#pragma unroll 4
        for (int d = 0; d < 64; d++) {
            float4 x0 = *(const float4*)&qw[d * 68 + (ty << 2)];
            float4 x1 = *(const float4*)&qr[d * 68 + (ty << 2)];
            float4 y0 = *(const float4*)&ks[d * 68 + (tx << 2)];
            float4 r0 = *(const float4*)&rks[d * 128 + cb_ - 3];
            float4 r1 = *(const float4*)&rks[d * 128 + cb_ + 1];
            float aw[4] = {x0.x, x0.y, x0.z, x0.w};
            float ar[4] = {x1.x, x1.y, x1.z, x1.w};
            float kv[4] = {y0.x, y0.y, y0.z, y0.w};
            float rr[8] = {r0.x, r0.y, r0.z, r0.w, r1.x, r1.y, r1.z, r1.w};
#pragma unroll
            for (int a = 0; a < 4; a++)
#pragma unroll
                for (int c = 0; c < 4; c++)
                    s[a][c] = fmaf(aw[a], kv[c], fmaf(ar[a], rr[3 + a - c], s[a][c]));
        }

        // scale + causal mask + online softmax (row group = half warp)
#pragma unroll
        for (int a = 0; a < 4; a++) {
            const int gi = i0 + (ty << 2) + a;
            float mx = -1e30f;
#pragma unroll
            for (int c = 0; c < 4; c++) {
                const int gj = j0 + (tx << 2) + c;
                float v = s[a][c] * SCALEC;
                if (gj > gi) v = NEGC;
                s[a][c] = v;
                mx = fmaxf(mx, v);
            }
#pragma unroll
            for (int off = 1; off < 16; off <<= 1)
                mx = fmaxf(mx, __shfl_xor_sync(0xffffffffu, mx, off, 16));
            const float mnew = fmaxf(m_r[a], mx);
            const float corr = __expf(m_r[a] - mnew);
            float psum = 0.f;
#pragma unroll
            for (int c = 0; c < 4; c++) {
                const float p = __expf(s[a][c] - mnew);
                s[a][c] = p;
                psum += p;
            }
#pragma unroll
            for (int off = 1; off < 16; off <<= 1)
                psum += __shfl_xor_sync(0xffffffffu, psum, off, 16);
            l_r[a] = l_r[a] * corr + psum;
            m_r[a] = mnew;
#pragma unroll
            for (int c = 0; c < 4; c++) oacc[a][c] *= corr;
        }
        // p -> shared, transposed to [j][i]
#pragma unroll
        for (int c = 0; c < 4; c++) {
            *(float4*)&ps[((tx << 2) + c) * 68 + (ty << 2)] =
                make_float4(s[0][c], s[1][c], s[2][c], s[3][c]);
        }
        __syncthreads();
        // PV accumulate: o[i][dd] += p[i][j] * v[j][dd]
#pragma unroll 8
        for (int j = 0; j < 64; j++) {
            float4 p4 = *(const float4*)&ps[j * 68 + (ty << 2)];
            float4 v4 = *(const float4*)&vs[j * 68 + (tx << 2)];
            float pv[4] = {p4.x, p4.y, p4.z, p4.w};
            float vv[4] = {v4.x, v4.y, v4.z, v4.w};
#pragma unroll
            for (int a = 0; a < 4; a++)
#pragma unroll
                for (int c = 0; c < 4; c++)
                    oacc[a][c] = fmaf(pv[a], vv[c], oacc[a][c]);
        }
    }
#pragma unroll
    for (int a = 0; a < 4; a++) {
        const float inv = 1.f / l_r[a];
        float* op = attv +
            (size_t)(((i0 + (ty << 2) + a) * BSZC + b) * NHC + n) * DHC + (tx << 2);
        *(float4*)op = make_float4(oacc[a][0] * inv, oacc[a][1] * inv,
                                   oacc[a][2] * inv, oacc[a][3] * inv);
    }
}

// ---------------- residual + LayerNorm ----------------
__global__ __launch_bounds__(256)
void ln_kernel(const float* __restrict__ w, const float* __restrict__ ao,
               const float* __restrict__ gamma, const float* __restrict__ beta,
               float* __restrict__ out)
{
    __shared__ float red[16];
    const int row = blockIdx.x, t = threadIdx.x;
    const size_t base = (size_t)row * DMC + t * 4;
    const float4 wv = *(const float4*)(w + base);
    const float4 av = *(const float4*)(ao + base);
    float x[4] = {wv.x + av.x, wv.y + av.y, wv.z + av.z, wv.w + av.w};
    float s1 = x[0] + x[1] + x[2] + x[3];
    float s2 = x[0]*x[0] + x[1]*x[1] + x[2]*x[2] + x[3]*x[3];
#pragma unroll
    for (int off = 16; off; off >>= 1) {
        s1 += __shfl_xor_sync(0xffffffffu, s1, off);
        s2 += __shfl_xor_sync(0xffffffffu, s2, off);
    }
    if ((t & 31) == 0) { red[t >> 5] = s1; red[8 + (t >> 5)] = s2; }
    __syncthreads();
    float ts1 = 0.f, ts2 = 0.f;
#pragma unroll
    for (int i = 0; i < 8; i++) { ts1 += red[i]; ts2 += red[8 + i]; }
    const float mu   = ts1 * (1.f / DMC);
    const float var  = ts2 * (1.f / DMC) - mu * mu;
    const float rstd = rsqrtf(var + 1e-5f);
    const float4 gv = *(const float4*)(gamma + t * 4);
    const float4 bv = *(const float4*)(beta + t * 4);
    float4 o;
    o.x = (x[0] - mu) * rstd * gv.x + bv.x;
    o.y = (x[1] - mu) * rstd * gv.y + bv.y;
    o.z = (x[2] - mu) * rstd * gv.z + bv.z;
    o.w = (x[3] - mu) * rstd * gv.w + bv.w;
    *(float4*)(out + base) = o;
}

// ---------------- launcher ----------------
extern "C" void kernel_launch(void* const* d_in, const int* in_sizes, int n_in,
                              void* d_out, int out_size)
{
    (void)in_sizes; (void)n_in; (void)out_size;
    const float* w    = (const float*)d_in[0];
    const float* r    = (const float*)d_in[1];
    const float* rwb  = (const float*)d_in[2];
    const float* rrb  = (const float*)d_in[3];
    const float* Wqkv = (const float*)d_in[4];
    const float* Wr   = (const float*)d_in[5];
    const float* Wo   = (const float*)d_in[6];
    const float* cwq  = (const float*)d_in[7];
    const float* cbq  = (const float*)d_in[8];
    const float* cwk  = (const float*)d_in[9];
    const float* cbk  = (const float*)d_in[10];
    const float* cwv  = (const float*)d_in[11];
    const float* cbv  = (const float*)d_in[12];
    const float* gam  = (const float*)d_in[13];
    const float* bet  = (const float*)d_in[14];
    // d_in[15] = causal mask, structurally known -> ignored

    float *heads, *qh, *kh, *vh, *rkb, *attv, *aout;
    uint32_t *wtq, *wtk, *wtv;
    cudaGetSymbolAddress((void**)&heads, g_heads);
    cudaGetSymbolAddress((void**)&qh,    g_qh);
    cudaGetSymbolAddress((void**)&kh,    g_kh);
    cudaGetSymbolAddress((void**)&vh,    g_vh);
    cudaGetSymbolAddress((void**)&rkb,   g_rk);
    cudaGetSymbolAddress((void**)&attv,  g_attv);
    cudaGetSymbolAddress((void**)&aout,  g_aout);
    cudaGetSymbolAddress((void**)&wtq,   g_wtq);
    cudaGetSymbolAddress((void**)&wtk,   g_wtk);
    cudaGetSymbolAddress((void**)&wtv,   g_wtv);

    cudaFuncSetAttribute(attn_kernel,
                         cudaFuncAttributeMaxDynamicSharedMemorySize, SMEM_ATT);

    // 0. conv weight transforms (tiny)
    wt_xform<<<112, 256>>>(cwq, wtq);
    wt_xform<<<112, 256>>>(cwk, wtk);
    wt_xform<<<112, 256>>>(cwv, wtv);
    // 1. heads = w @ W_qkv^T   [4096 x 3072]
    sgemm_tf32<<<dim3(H3C / 128, ROWSC / 128), 256>>>(w, Wqkv, heads, ROWSC, H3C, DMC);
    // 2. r_head_k = r @ W_r^T  [1024 x 1024]
    sgemm_tf32<<<dim3(DMC / 128, QLENC / 128), 256>>>(r, Wr, rkb, QLENC, DMC, DMC);
    // 3. convs (tensor-core shifted GEMM)
    conv_mma<<<dim3(8, 64), 256>>>(heads, 0,       wtq, cbq, qh);
    conv_mma<<<dim3(8, 64), 256>>>(heads, DMC,     wtk, cbk, kh);
    conv_mma<<<dim3(8, 64), 256>>>(heads, 2 * DMC, wtv, cbv, vh);
    // 4. fused rel-attention
    attn_kernel<<<dim3(16, 4, 16), 256, SMEM_ATT>>>(qh, kh, vh, rkb, rwb, rrb, attv);
    // 5. out projection
    sgemm_tf32<<<dim3(DMC / 128, ROWSC / 128), 256>>>(attv, Wo, aout, ROWSC, DMC, DMC);
    // 6. residual + LN
    ln_kernel<<<ROWSC, 256>>>(w, aout, gam, bet, (float*)d_out);
}

// round 3
// speedup vs baseline: 3.5168x; 2.0735x over previous
#include <cuda_runtime.h>
#include <cstdint>

#define QLENC 1024
#define BSZC  4
#define NHC   16
#define DHC   64
#define DMC   1024
#define H3C   3072
#define ROWSC 4096   // QLEN*BSZ
#define CONVC 7
#define SCALEC 0.125f
#define NEGC  -1e30f

// ---------------- scratch (no allocation allowed) ----------------
__device__ float g_heads[(size_t)ROWSC * H3C];   // [row=q*4+b][3*N*D]
__device__ float g_qh[(size_t)ROWSC * DMC];      // [l][b][n][d]
__device__ float g_kh[(size_t)ROWSC * DMC];
__device__ float g_vh[(size_t)ROWSC * DMC];
__device__ float g_rk[(size_t)QLENC * DMC];      // [rho][n][d]
__device__ float g_attv[(size_t)ROWSC * DMC];    // [row][n*64+d]
__device__ float g_aout[(size_t)ROWSC * DMC];
__device__ uint32_t g_wtq[448 * 64];             // conv weights, [k*64+i][o], tf32 bits
__device__ uint32_t g_wtk[448 * 64];
__device__ uint32_t g_wtv[448 * 64];

// ---------------- helpers ----------------
__device__ __forceinline__ uint32_t f2tf(float x) {
    uint32_t r;
    asm("cvt.rna.tf32.f32 %0, %1;" : "=r"(r) : "f"(x));
    return r;
}

__device__ __forceinline__ void mma_tf32(float c[4], const uint32_t a[4],
                                         const uint32_t b[2]) {
    asm volatile(
        "mma.sync.aligned.m16n8k8.row.col.f32.tf32.tf32.f32 "
        "{%0,%1,%2,%3}, {%4,%5,%6,%7}, {%8,%9}, {%0,%1,%2,%3};"
        : "+f"(c[0]), "+f"(c[1]), "+f"(c[2]), "+f"(c[3])
        : "r"(a[0]), "r"(a[1]), "r"(a[2]), "r"(a[3]), "r"(b[0]), "r"(b[1]));
}

__device__ __forceinline__ void ldsm4(uint32_t d[4], const float* p) {
    uint32_t a = (uint32_t)__cvta_generic_to_shared(p);
    asm volatile("ldmatrix.sync.aligned.m8n8.x4.shared.b16 {%0,%1,%2,%3}, [%4];"
                 : "=r"(d[0]), "=r"(d[1]), "=r"(d[2]), "=r"(d[3]) : "r"(a));
}

__device__ __forceinline__ void cpa16(float* s, const float* g) {
    uint32_t sa = (uint32_t)__cvta_generic_to_shared(s);
    asm volatile("cp.async.cg.shared.global [%0], [%1], 16;" :: "r"(sa), "l"(g));
}
#define CP_COMMIT() asm volatile("cp.async.commit_group;")
#define CP_WAIT2()  asm volatile("cp.async.wait_group 2;")

// ---------------- TF32 SGEMM: C[M,N] = A[M,K] * B[N,K]^T ----------------
// Block 128x128, 8 warps (warp 64x32), k-chunk 16, cp.async 4-stage, ldmatrix.
#define GEMM_SMEM (2 * 4 * 128 * 20 * 4)
__global__ __launch_bounds__(256, 2)
void sgemm_tf32(const float* __restrict__ A, const float* __restrict__ B,
                float* __restrict__ C, int M, int N, int K)
{
    extern __shared__ float sh[];
    float* As = sh;             // [4][128][20]
    float* Bs = sh + 4 * 128 * 20;
    const int t = threadIdx.x, warp = t >> 5, lane = t & 31;
    const int r = lane >> 2, cl = lane & 3, g = lane >> 3, i_ = lane & 7;
    const int wm = (warp >> 2) * 64, wn = (warp & 3) * 32;
    const int m0 = blockIdx.y << 7, n0 = blockIdx.x << 7;
    const int srow = t >> 1, sc = (t & 1) << 3;

    const float* Ab = A + (size_t)(m0 + srow) * K + sc;
    const float* Bb = B + (size_t)(n0 + srow) * K + sc;
    float* Asw = As + srow * 20 + sc;
    float* Bsw = Bs + srow * 20 + sc;
    const int nk = K >> 4;

    float acc[4][4][4];
#pragma unroll
    for (int mf = 0; mf < 4; mf++)
#pragma unroll
        for (int nf = 0; nf < 4; nf++)
#pragma unroll
            for (int q = 0; q < 4; q++) acc[mf][nf][q] = 0.f;

#pragma unroll
    for (int s = 0; s < 3; s++) {
        cpa16(Asw + s * 2560,     Ab + s * 16);
        cpa16(Asw + s * 2560 + 4, Ab + s * 16 + 4);
        cpa16(Bsw + s * 2560,     Bb + s * 16);
        cpa16(Bsw + s * 2560 + 4, Bb + s * 16 + 4);
        CP_COMMIT();
    }

    const int acoff = (g >> 1) << 2, aroff = ((g & 1) << 3) + i_;
    const int bcoff = (g & 1) << 2,  broff = ((g >> 1) << 3) + i_;

    for (int kt = 0; kt < nk; kt++) {
        CP_WAIT2();
        __syncthreads();
        if (kt + 3 < nk) {
            const int st = (kt + 3) & 3;
            cpa16(Asw + st * 2560,     Ab + (kt + 3) * 16);
            cpa16(Asw + st * 2560 + 4, Ab + (kt + 3) * 16 + 4);
            cpa16(Bsw + st * 2560,     Bb + (kt + 3) * 16);
            cpa16(Bsw + st * 2560 + 4, Bb + (kt + 3) * 16 + 4);
            CP_COMMIT();
        }
        const float* Ac = As + (kt & 3) * 2560;
        const float* Bc = Bs + (kt & 3) * 2560;
#pragma unroll
        for (int ks = 0; ks < 2; ks++) {
            uint32_t af[4][4], bf[2][4];
#pragma unroll
            for (int mf = 0; mf < 4; mf++)
                ldsm4(af[mf], Ac + (wm + mf * 16 + aroff) * 20 + ks * 8 + acoff);
#pragma unroll
            for (int p = 0; p < 2; p++)
                ldsm4(bf[p], Bc + (wn + p * 16 + broff) * 20 + ks * 8 + bcoff);
#pragma unroll
            for (int mf = 0; mf < 4; mf++)
#pragma unroll
                for (int nf = 0; nf < 4; nf++) {
                    uint32_t bb[2] = { bf[nf >> 1][(nf & 1) * 2],
                                       bf[nf >> 1][(nf & 1) * 2 + 1] };
                    mma_tf32(acc[mf][nf], af[mf], bb);
                }
        }
    }

#pragma unroll
    for (int mf = 0; mf < 4; mf++) {
#pragma unroll
        for (int nf = 0; nf < 4; nf++) {
            const int row = m0 + wm + mf * 16 + r;
            const int col = n0 + wn + nf * 8 + (cl << 1);
            *(float2*)(C + (size_t)row * N + col) =
                make_float2(acc[mf][nf][0], acc[mf][nf][1]);
            *(float2*)(C + (size_t)(row + 8) * N + col) =
                make_float2(acc[mf][nf][2], acc[mf][nf][3]);
        }
    }
}

// ---------------- conv weight transform: cw[O][I][K] -> wt[k*64+i][o] tf32 ---
__global__ void wt_xform(const float* __restrict__ cw, uint32_t* __restrict__ wt)
{
    const int idx = blockIdx.x * 256 + threadIdx.x;
    if (idx >= 448 * 64) return;
    const int kidx = idx >> 6, o = idx & 63;
    const int i = kidx & 63, k = kidx >> 6;
    wt[idx] = f2tf(cw[(o * 64 + i) * CONVC + k]);
}

// ---------------- conv1d as shifted GEMM on tensor cores -------------------
__global__ __launch_bounds__(256)
void conv_mma(const float* __restrict__ heads, int colbase,
              const uint32_t* __restrict__ wt, const float* __restrict__ cb,
              float* __restrict__ out)
{
    __shared__ uint32_t xs[134][68];   // [l - l0 + 3][i], tf32 bits
    __shared__ uint32_t bs[32][72];    // [ii][o]
    const int t = threadIdx.x;
    const int warp = t >> 5, lane = t & 31;
    const int wm = (warp >> 1) * 32, wn = (warp & 1) * 32;
    const int r = lane >> 2, c = lane & 3;
    const int nb = blockIdx.y;
    const int n = nb >> 2, b = nb & 3;
    const int l0 = blockIdx.x << 7;

    for (int u = t; u < 134 * 16; u += 256) {
        const int row = u >> 4, i4 = (u & 15) << 2;
        const int gl = l0 + row - 3;
        float4 v = make_float4(0.f, 0.f, 0.f, 0.f);
        if (gl >= 0 && gl < QLENC)
            v = *(const float4*)(heads + (size_t)(gl * BSZC + b) * H3C +
                                 colbase + n * DHC + i4);
        xs[row][i4]     = f2tf(v.x);
        xs[row][i4 + 1] = f2tf(v.y);
        xs[row][i4 + 2] = f2tf(v.z);
        xs[row][i4 + 3] = f2tf(v.w);
    }

    float acc[2][4][4];
#pragma unroll
    for (int mf = 0; mf < 2; mf++)
#pragma unroll
        for (int nf = 0; nf < 4; nf++)
#pragma unroll
            for (int q = 0; q < 4; q++) acc[mf][nf][q] = 0.f;

    for (int chunk = 0; chunk < 14; chunk++) {
        const int k = chunk >> 1;
        const int ibase = (chunk & 1) << 5;
        __syncthreads();
        for (int u = t; u < 32 * 16; u += 256) {
            const int ii = u >> 4, o4 = (u & 15) << 2;
            *(uint4*)&bs[ii][o4] =
                *(const uint4*)(wt + ((size_t)(k * 64 + ibase + ii) << 6) + o4);
        }
        __syncthreads();

#pragma unroll
        for (int ks = 0; ks < 4; ks++) {
            const int kb = ks << 3;
            uint32_t af[2][4];
#pragma unroll
            for (int mf = 0; mf < 2; mf++) {
                const int m = wm + mf * 16 + r;
                af[mf][0] = xs[m + k][ibase + kb + c];
                af[mf][1] = xs[m + 8 + k][ibase + kb + c];
                af[mf][2] = xs[m + k][ibase + kb + c + 4];
                af[mf][3] = xs[m + 8 + k][ibase + kb + c + 4];
            }
            uint32_t bf[4][2];
#pragma unroll
            for (int nf = 0; nf < 4; nf++) {
                const int o = wn + nf * 8 + r;
                bf[nf][0] = bs[kb + c][o];
                bf[nf][1] = bs[kb + c + 4][o];
            }
#pragma unroll
            for (int mf = 0; mf < 2; mf++)
#pragma unroll
                for (int nf = 0; nf < 4; nf++)
                    mma_tf32(acc[mf][nf], af[mf], bf[nf]);
        }
    }

#pragma unroll
    for (int mf = 0; mf < 2; mf++) {
#pragma unroll
        for (int nf = 0; nf < 4; nf++) {
            const int gl = l0 + wm + mf * 16 + r;
            const int o = wn + nf * 8 + (c << 1);
            const float b0 = __ldg(cb + o), b1 = __ldg(cb + o + 1);
            float2* p0 = (float2*)(out + (size_t)((gl * BSZC + b) * NHC + n) * DHC + o);
            float2* p1 = (float2*)(out + (size_t)(((gl + 8) * BSZC + b) * NHC + n) * DHC + o);
            *p0 = make_float2(acc[mf][nf][0] + b0, acc[mf][nf][1] + b1);
            *p1 = make_float2(acc[mf][nf][2] + b0, acc[mf][nf][3] + b1);
        }
    }
}

// ---------------- fused rel-attention with tensor-core MMA -----------------
// score[i,j] = (q_i+rwb)·k_j + (q_i+rrb)·rk[1023-(i-j)]   (j<=i)
// S = Qw·K^T (mma), T[i][x] = Qr·Rks^T (mma over 127-wide delta window),
// softmax gathers T[i][i-j+63]; PV via mma with V^T in smem.
#define ATT_SMEM (39296 * 4)
__global__ __launch_bounds__(256)
void attn_mma(const float* __restrict__ qh, const float* __restrict__ kh,
              const float* __restrict__ vh, const float* __restrict__ rk,
              const float* __restrict__ rwb, const float* __restrict__ rrb,
              float* __restrict__ attv)
{
    extern __shared__ float sh[];
    float* qw_s   = sh;            // [64][68]  (i, d)
    float* qr_s   = sh + 4352;     // [64][68]
    float* k_s    = sh + 8704;     // [64][68]  (j, d)
    float* v_s    = sh + 13056;    // [64][68]  (d, j)  transposed
    float* s_s    = sh + 17408;    // [64][68]  scores, then P
    float* rk_s   = sh + 21760;    // [128][68] (x, d)
    float* t_s    = sh + 30464;    // [64][136] (i, x)
    float* corr_s = sh + 39168;    // [64]
    float* linv_s = sh + 39232;    // [64]

    const int i0 = blockIdx.x << 6, b = blockIdx.y, n = blockIdx.z;
    const int t = threadIdx.x, warp = t >> 5, lane = t & 31;
    const int r = lane >> 2, cl = lane & 3, g = lane >> 3, i_ = lane & 7;
    const int wi = warp >> 1, wj = warp & 1;
    const int ty = t >> 4, tx = t & 15;

    // load Q tiles with biases
    for (int u = t; u < 1024; u += 256) {
        const int il = u >> 4, d4 = (u & 15) << 2;
        const float4 qv = *(const float4*)(qh +
            ((size_t)((i0 + il) * BSZC + b) * NHC + n) * DHC + d4);
        const float4 wv = *(const float4*)(rwb + n * DHC + d4);
        const float4 rv = *(const float4*)(rrb + n * DHC + d4);
        *(float4*)&qw_s[il * 68 + d4] =
            make_float4(qv.x + wv.x, qv.y + wv.y, qv.z + wv.z, qv.w + wv.w);
        *(float4*)&qr_s[il * 68 + d4] =
            make_float4(qv.x + rv.x, qv.y + rv.y, qv.z + rv.z, qv.w + rv.w);
    }

    float oacc[4][4];
#pragma unroll
    for (int nf = 0; nf < 4; nf++)
#pragma unroll
        for (int q = 0; q < 4; q++) oacc[nf][q] = 0.f;
    float m_r[4], l_r[4];
#pragma unroll
    for (int a = 0; a < 4; a++) { m_r[a] = -1e30f; l_r[a] = 0.f; }

    const int acoff = (g >> 1) << 2, aroff = ((g & 1) << 3) + i_;
    const int bcoff = (g & 1) << 2,  broff = ((g >> 1) << 3) + i_;

    for (int j0 = 0; j0 <= i0; j0 += 64) {
        __syncthreads();
        // K, V(transposed)
        for (int u = t; u < 1024; u += 256) {
            const int jl = u >> 4, d4 = (u & 15) << 2;
            const size_t gi = ((size_t)((j0 + jl) * BSZC + b) * NHC + n) * DHC + d4;
            *(float4*)&k_s[jl * 68 + d4] = *(const float4*)(kh + gi);
            const float4 vv = *(const float4*)(vh + gi);
            v_s[(d4 + 0) * 68 + jl] = vv.x;
            v_s[(d4 + 1) * 68 + jl] = vv.y;
            v_s[(d4 + 2) * 68 + jl] = vv.z;
            v_s[(d4 + 3) * 68 + jl] = vv.w;
        }
        // rel window
        const int dbase = i0 - j0 - 63;
        for (int u = t; u < 2048; u += 256) {
            const int x = u >> 4, d4 = (u & 15) << 2;
            const int drel = dbase + x;
            float4 rv = make_float4(0.f, 0.f, 0.f, 0.f);
            if (drel >= 0 && drel < QLENC)
                rv = *(const float4*)(rk + (size_t)(QLENC - 1 - drel) * DMC +
                                      n * DHC + d4);
            *(float4*)&rk_s[x * 68 + d4] = rv;
        }
        __syncthreads();

        // S = Qw K^T  (warp: rows wi*16, cols wj*32)
        {
            float cf[4][4];
#pragma unroll
            for (int nf = 0; nf < 4; nf++)
#pragma unroll
                for (int q = 0; q < 4; q++) cf[nf][q] = 0.f;
            const float* arow = qw_s + (wi * 16 + aroff) * 68 + acoff;
            const float* brow = k_s + (wj * 32 + broff) * 68 + bcoff;
#pragma unroll
            for (int ks = 0; ks < 8; ks++) {
                uint32_t a4[4], b4[2][4];
                ldsm4(a4, arow + ks * 8);
                ldsm4(b4[0], brow + ks * 8);
                ldsm4(b4[1], brow + 16 * 68 + ks * 8);
#pragma unroll
                for (int nf = 0; nf < 4; nf++) {
                    uint32_t bb[2] = { b4[nf >> 1][(nf & 1) * 2],
                                       b4[nf >> 1][(nf & 1) * 2 + 1] };
                    mma_tf32(cf[nf], a4, bb);
                }
            }
            const int sr = wi * 16 + r;
#pragma unroll
            for (int nf = 0; nf < 4; nf++) {
                const int col = wj * 32 + nf * 8 + (cl << 1);
                *(float2*)&s_s[sr * 68 + col]       = make_float2(cf[nf][0], cf[nf][1]);
                *(float2*)&s_s[(sr + 8) * 68 + col] = make_float2(cf[nf][2], cf[nf][3]);
            }
        }
        // T = Qr Rks^T  (warp: rows wi*16, cols wj*64)
        {
            float cf[8][4];
#pragma unroll
            for (int nf = 0; nf < 8; nf++)
#pragma unroll
                for (int q = 0; q < 4; q++) cf[nf][q] = 0.f;
            const float* arow = qr_s + (wi * 16 + aroff) * 68 + acoff;
            const float* brow = rk_s + (wj * 64 + broff) * 68 + bcoff;
#pragma unroll
            for (int ks = 0; ks < 8; ks++) {
                uint32_t a4[4], b4[4][4];
                ldsm4(a4, arow + ks * 8);
#pragma unroll
                for (int p = 0; p < 4; p++)
                    ldsm4(b4[p], brow + p * 16 * 68 + ks * 8);
#pragma unroll
                for (int nf = 0; nf < 8; nf++) {
                    uint32_t bb[2] = { b4[nf >> 1][(nf & 1) * 2],
                                       b4[nf >> 1][(nf & 1) * 2 + 1] };
                    mma_tf32(cf[nf], a4, bb);
                }
            }
            const int sr = wi * 16 + r;
#pragma unroll
            for (int nf = 0; nf < 8; nf++) {
                const int col = wj * 64 + nf * 8 + (cl << 1);
                *(float2*)&t_s[sr * 136 + col]       = make_float2(cf[nf][0], cf[nf][1]);
                *(float2*)&t_s[(sr + 8) * 136 + col] = make_float2(cf[nf][2], cf[nf][3]);
            }
        }
        __syncthreads();

        // softmax (thread owns rows il = 4ty+a, cols 4tx..4tx+3)
#pragma unroll
        for (int a = 0; a < 4; a++) {
            const int il = (ty << 2) + a;
            const int gi = i0 + il;
            const float4 sv = *(const float4*)&s_s[il * 68 + (tx << 2)];
            float s4[4] = {sv.x, sv.y, sv.z, sv.w};
            float mx = -1e30f;
#pragma unroll
            for (int c = 0; c < 4; c++) {
                const int jl = (tx << 2) + c;
                const float tv = t_s[il * 136 + (il - jl + 63)];
                float v = (s4[c] + tv) * SCALEC;
                if (j0 + jl > gi) v = NEGC;
                s4[c] = v;
                mx = fmaxf(mx, v);
            }
#pragma unroll
            for (int off = 1; off < 16; off <<= 1)
                mx = fmaxf(mx, __shfl_xor_sync(0xffffffffu, mx, off, 16));
            const float mnew = fmaxf(m_r[a], mx);
            const float corr = __expf(m_r[a] - mnew);
            float psum = 0.f;
#pragma unroll
            for (int c = 0; c < 4; c++) {
                s4[c] = __expf(s4[c] - mnew);
                psum += s4[c];
            }
#pragma unroll
            for (int off = 1; off < 16; off <<= 1)
                psum += __shfl_xor_sync(0xffffffffu, psum, off, 16);
            l_r[a] = l_r[a] * corr + psum;
            m_r[a] = mnew;
            if (tx == 0) corr_s[il] = corr;
            *(float4*)&s_s[il * 68 + (tx << 2)] =
                make_float4(s4[0], s4[1], s4[2], s4[3]);
        }
        __syncthreads();

        // PV: O += P V   (warp: rows wi*16, cols(d) wj*32)
        {
            const float c0 = corr_s[wi * 16 + r], c1 = corr_s[wi * 16 + 8 + r];
#pragma unroll
            for (int nf = 0; nf < 4; nf++) {
                oacc[nf][0] *= c0; oacc[nf][1] *= c0;
                oacc[nf][2] *= c1; oacc[nf][3] *= c1;
            }
            const float* arow = s_s + (wi * 16 + aroff) * 68 + acoff;
            const float* brow = v_s + (wj * 32 + broff) * 68 + bcoff;
#pragma unroll
            for (int ks = 0; ks < 8; ks++) {
                uint32_t a4[4], b4[2][4];
                ldsm4(a4, arow + ks * 8);
                ldsm4(b4[0], brow + ks * 8);
                ldsm4(b4[1], brow + 16 * 68 + ks * 8);
#pragma unroll
                for (int nf = 0; nf < 4; nf++) {
                    uint32_t bb[2] = { b4[nf >> 1][(nf & 1) * 2],
                                       b4[nf >> 1][(nf & 1) * 2 + 1] };
                    mma_tf32(oacc[nf], a4, bb);
                }
            }
        }
    }

    if (tx == 0) {
#pragma unroll
        for (int a = 0; a < 4; a++) linv_s[(ty << 2) + a] = 1.f / l_r[a];
    }
    __syncthreads();
    {
        const int ir0 = i0 + wi * 16 + r;
        const float li0 = linv_s[wi * 16 + r], li1 = linv_s[wi * 16 + 8 + r];
#pragma unroll
        for (int nf = 0; nf < 4; nf++) {
            const int d = wj * 32 + nf * 8 + (cl << 1);
            *(float2*)(attv + ((size_t)(ir0 * BSZC + b) * NHC + n) * DHC + d) =
                make_float2(oacc[nf][0] * li0, oacc[nf][1] * li0);
            *(float2*)(attv + ((size_t)((ir0 + 8) * BSZC + b) * NHC + n) * DHC + d) =
                make_float2(oacc[nf][2] * li1, oacc[nf][3] * li1);
        }
    }
}

// ---------------- residual + LayerNorm ----------------
__global__ __launch_bounds__(256)
void ln_kernel(const float* __restrict__ w, const float* __restrict__ ao,
               const float* __restrict__ gamma, const float* __restrict__ beta,
               float* __restrict__ out)
{
    __shared__ float red[16];
    const int row = blockIdx.x, t = threadIdx.x;
    const size_t base = (size_t)row * DMC + t * 4;
    const float4 wv = *(const float4*)(w + base);
    const float4 av = *(const float4*)(ao + base);
    float x[4] = {wv.x + av.x, wv.y + av.y, wv.z + av.z, wv.w + av.w};
    float s1 = x[0] + x[1] + x[2] + x[3];
    float s2 = x[0]*x[0] + x[1]*x[1] + x[2]*x[2] + x[3]*x[3];
#pragma unroll
    for (int off = 16; off; off >>= 1) {
        s1 += __shfl_xor_sync(0xffffffffu, s1, off);
        s2 += __shfl_xor_sync(0xffffffffu, s2, off);
    }
    if ((t & 31) == 0) { red[t >> 5] = s1; red[8 + (t >> 5)] = s2; }
    __syncthreads();
    float ts1 = 0.f, ts2 = 0.f;
#pragma unroll
    for (int i = 0; i < 8; i++) { ts1 += red[i]; ts2 += red[8 + i]; }
    const float mu   = ts1 * (1.f / DMC);
    const float var  = ts2 * (1.f / DMC) - mu * mu;
    const float rstd = rsqrtf(var + 1e-5f);
    const float4 gv = *(const float4*)(gamma + t * 4);
    const float4 bv = *(const float4*)(beta + t * 4);
    float4 o;
    o.x = (x[0] - mu) * rstd * gv.x + bv.x;
    o.y = (x[1] - mu) * rstd * gv.y + bv.y;
    o.z = (x[2] - mu) * rstd * gv.z + bv.z;
    o.w = (x[3] - mu) * rstd * gv.w + bv.w;
    *(float4*)(out + base) = o;
}

// ---------------- launcher ----------------
extern "C" void kernel_launch(void* const* d_in, const int* in_sizes, int n_in,
                              void* d_out, int out_size)
{
    (void)in_sizes; (void)n_in; (void)out_size;
    const float* w    = (const float*)d_in[0];
    const float* r    = (const float*)d_in[1];
    const float* rwb  = (const float*)d_in[2];
    const float* rrb  = (const float*)d_in[3];
    const float* Wqkv = (const float*)d_in[4];
    const float* Wr   = (const float*)d_in[5];
    const float* Wo   = (const float*)d_in[6];
    const float* cwq  = (const float*)d_in[7];
    const float* cbq  = (const float*)d_in[8];
    const float* cwk  = (const float*)d_in[9];
    const float* cbk  = (const float*)d_in[10];
    const float* cwv  = (const float*)d_in[11];
    const float* cbv  = (const float*)d_in[12];
    const float* gam  = (const float*)d_in[13];
    const float* bet  = (const float*)d_in[14];

    float *heads, *qh, *kh, *vh, *rkb, *attv, *aout;
    uint32_t *wtq, *wtk, *wtv;
    cudaGetSymbolAddress((void**)&heads, g_heads);
    cudaGetSymbolAddress((void**)&qh,    g_qh);
    cudaGetSymbolAddress((void**)&kh,    g_kh);
    cudaGetSymbolAddress((void**)&vh,    g_vh);
    cudaGetSymbolAddress((void**)&rkb,   g_rk);
    cudaGetSymbolAddress((void**)&attv,  g_attv);
    cudaGetSymbolAddress((void**)&aout,  g_aout);
    cudaGetSymbolAddress((void**)&wtq,   g_wtq);
    cudaGetSymbolAddress((void**)&wtk,   g_wtk);
    cudaGetSymbolAddress((void**)&wtv,   g_wtv);

    cudaFuncSetAttribute(sgemm_tf32,
                         cudaFuncAttributeMaxDynamicSharedMemorySize, GEMM_SMEM);
    cudaFuncSetAttribute(attn_mma,
                         cudaFuncAttributeMaxDynamicSharedMemorySize, ATT_SMEM);

    // 0. conv weight transforms (tiny)
    wt_xform<<<112, 256>>>(cwq, wtq);
    wt_xform<<<112, 256>>>(cwk, wtk);
    wt_xform<<<112, 256>>>(cwv, wtv);
    // 1. heads = w @ W_qkv^T   [4096 x 3072]
    sgemm_tf32<<<dim3(H3C / 128, ROWSC / 128), 256, GEMM_SMEM>>>(
        w, Wqkv, heads, ROWSC, H3C, DMC);
    // 2. r_head_k = r @ W_r^T  [1024 x 1024]
    sgemm_tf32<<<dim3(DMC / 128, QLENC / 128), 256, GEMM_SMEM>>>(
        r, Wr, rkb, QLENC, DMC, DMC);
    // 3. convs (tensor-core shifted GEMM)
    conv_mma<<<dim3(8, 64), 256>>>(heads, 0,       wtq, cbq, qh);
    conv_mma<<<dim3(8, 64), 256>>>(heads, DMC,     wtk, cbk, kh);
    conv_mma<<<dim3(8, 64), 256>>>(heads, 2 * DMC, wtv, cbv, vh);
    // 4. fused rel-attention on tensor cores
    attn_mma<<<dim3(16, 4, 16), 256, ATT_SMEM>>>(qh, kh, vh, rkb, rwb, rrb, attv);
    // 5. out projection
    sgemm_tf32<<<dim3(DMC / 128, ROWSC / 128), 256, GEMM_SMEM>>>(
        attv, Wo, aout, ROWSC, DMC, DMC);
    // 6. residual + LN
    ln_kernel<<<ROWSC, 256>>>(w, aout, gam, bet, (float*)d_out);
}

// round 4
// speedup vs baseline: 4.2091x; 1.1969x over previous
#include <cuda_runtime.h>
#include <cuda_bf16.h>
#include <cstdint>

#define QLENC 1024
#define BSZC  4
#define NHC   16
#define DHC   64
#define DMC   1024
#define H3C   3072
#define ROWSC 4096   // QLEN*BSZ
#define CONVC 7
#define SCALEC 0.125f
#define NEGC  -1e30f

// ---------------- scratch (no allocation allowed) ----------------
__device__ float g_heads[(size_t)ROWSC * H3C];   // [row=q*4+b][3*N*D]
__device__ float g_qh[(size_t)ROWSC * DMC];      // [l][b][n][d]
__device__ float g_kh[(size_t)ROWSC * DMC];
__device__ float g_vh[(size_t)ROWSC * DMC];
__device__ float g_rk[(size_t)QLENC * DMC];      // [rho][n][d]
__device__ float g_attv[(size_t)ROWSC * DMC];    // [row][n*64+d]
__device__ float g_aout[(size_t)ROWSC * DMC];
__device__ uint32_t g_wtq[448 * 64];             // conv weights, [k*64+i][o], tf32 bits
__device__ uint32_t g_wtk[448 * 64];
__device__ uint32_t g_wtv[448 * 64];
// bf16 operand copies
__device__ __nv_bfloat16 g_bw[(size_t)ROWSC * DMC];
__device__ __nv_bfloat16 g_bqkv[(size_t)H3C * DMC];
__device__ __nv_bfloat16 g_br[(size_t)QLENC * DMC];
__device__ __nv_bfloat16 g_bwr[(size_t)DMC * DMC];
__device__ __nv_bfloat16 g_bwo[(size_t)DMC * DMC];
__device__ __nv_bfloat16 g_battv[(size_t)ROWSC * DMC];

// ---------------- helpers ----------------
__device__ __forceinline__ uint32_t f2tf(float x) {
    uint32_t r;
    asm("cvt.rna.tf32.f32 %0, %1;" : "=r"(r) : "f"(x));
    return r;
}

__device__ __forceinline__ void mma_tf32(float c[4], const uint32_t a[4],
                                         const uint32_t b[2]) {
    asm volatile(
        "mma.sync.aligned.m16n8k8.row.col.f32.tf32.tf32.f32 "
        "{%0,%1,%2,%3}, {%4,%5,%6,%7}, {%8,%9}, {%0,%1,%2,%3};"
        : "+f"(c[0]), "+f"(c[1]), "+f"(c[2]), "+f"(c[3])
        : "r"(a[0]), "r"(a[1]), "r"(a[2]), "r"(a[3]), "r"(b[0]), "r"(b[1]));
}

__device__ __forceinline__ void mma_bf16(float c[4], const uint32_t a[4],
                                         const uint32_t b[2]) {
    asm volatile(
        "mma.sync.aligned.m16n8k16.row.col.f32.bf16.bf16.f32 "
        "{%0,%1,%2,%3}, {%4,%5,%6,%7}, {%8,%9}, {%0,%1,%2,%3};"
        : "+f"(c[0]), "+f"(c[1]), "+f"(c[2]), "+f"(c[3])
        : "r"(a[0]), "r"(a[1]), "r"(a[2]), "r"(a[3]), "r"(b[0]), "r"(b[1]));
}

__device__ __forceinline__ void ldsm4(uint32_t d[4], const float* p) {
    uint32_t a = (uint32_t)__cvta_generic_to_shared(p);
    asm volatile("ldmatrix.sync.aligned.m8n8.x4.shared.b16 {%0,%1,%2,%3}, [%4];"
                 : "=r"(d[0]), "=r"(d[1]), "=r"(d[2]), "=r"(d[3]) : "r"(a));
}

__device__ __forceinline__ void ldsm4b(uint32_t d[4], const __nv_bfloat16* p) {
    uint32_t a = (uint32_t)__cvta_generic_to_shared(p);
    asm volatile("ldmatrix.sync.aligned.m8n8.x4.shared.b16 {%0,%1,%2,%3}, [%4];"
                 : "=r"(d[0]), "=r"(d[1]), "=r"(d[2]), "=r"(d[3]) : "r"(a));
}

__device__ __forceinline__ void cpa16(const void* s, const void* g) {
    uint32_t sa = (uint32_t)__cvta_generic_to_shared(s);
    asm volatile("cp.async.cg.shared.global [%0], [%1], 16;" :: "r"(sa), "l"(g));
}
#define CP_COMMIT() asm volatile("cp.async.commit_group;")
#define CP_WAIT2()  asm volatile("cp.async.wait_group 2;")

// ---------------- fp32 -> bf16 converts (fused) ----------------
__global__ __launch_bounds__(256)
void cvt5(const float* __restrict__ w, const float* __restrict__ Wqkv,
          const float* __restrict__ r, const float* __restrict__ Wr,
          const float* __restrict__ Wo,
          __nv_bfloat16* __restrict__ ow, __nv_bfloat16* __restrict__ oq,
          __nv_bfloat16* __restrict__ orr, __nv_bfloat16* __restrict__ owr,
          __nv_bfloat16* __restrict__ owo)
{
    int idx = blockIdx.x * 256 + threadIdx.x;   // float4 index
    const float* src; __nv_bfloat16* dst;
    if (idx < 1048576)      { src = w;    dst = ow; }
    else if (idx < 1835008) { src = Wqkv; dst = oq;  idx -= 1048576; }
    else if (idx < 2097152) { src = r;    dst = orr; idx -= 1835008; }
    else if (idx < 2359296) { src = Wr;   dst = owr; idx -= 2097152; }
    else                    { src = Wo;   dst = owo; idx -= 2359296; }
    const float4 v = *(const float4*)(src + (size_t)idx * 4);
    __nv_bfloat162* d2 = (__nv_bfloat162*)(dst + (size_t)idx * 4);
    d2[0] = __floats2bfloat162_rn(v.x, v.y);
    d2[1] = __floats2bfloat162_rn(v.z, v.w);
}

__global__ __launch_bounds__(256)
void cvt1(const float* __restrict__ src, __nv_bfloat16* __restrict__ dst)
{
    const int idx = blockIdx.x * 256 + threadIdx.x;
    const float4 v = *(const float4*)(src + (size_t)idx * 4);
    __nv_bfloat162* d2 = (__nv_bfloat162*)(dst + (size_t)idx * 4);
    d2[0] = __floats2bfloat162_rn(v.x, v.y);
    d2[1] = __floats2bfloat162_rn(v.z, v.w);
}

// ---------------- BF16 GEMM: C[M,N] = A[M,K] * B[N,K]^T -------------------
// Block 128x128, 8 warps (warp 64x32), k-chunk 16, cp.async 4-stage, ldmatrix.
#define BG_SMEM (2 * 4 * 128 * 24 * 2)   // 49152 bytes
__global__ __launch_bounds__(256, 2)
void bgemm(const __nv_bfloat16* __restrict__ A, const __nv_bfloat16* __restrict__ B,
           float* __restrict__ C, int M, int N, int K)
{
    extern __shared__ __nv_bfloat16 shb[];
    __nv_bfloat16* As = shb;                 // [4][128][24]
    __nv_bfloat16* Bs = shb + 4 * 128 * 24;
    const int t = threadIdx.x, warp = t >> 5, lane = t & 31;
    const int r = lane >> 2, cl = lane & 3, g = lane >> 3, i_ = lane & 7;
    const int wm = (warp >> 2) * 64, wn = (warp & 3) * 32;
    const int m0 = blockIdx.y << 7, n0 = blockIdx.x << 7;
    const int srow = t >> 1, sc = (t & 1) << 3;

    const __nv_bfloat16* Ab = A + (size_t)(m0 + srow) * K + sc;
    const __nv_bfloat16* Bb = B + (size_t)(n0 + srow) * K + sc;
    __nv_bfloat16* Asw = As + srow * 24 + sc;
    __nv_bfloat16* Bsw = Bs + srow * 24 + sc;
    const int nk = K >> 4;

    float acc[4][4][4];
#pragma unroll
    for (int mf = 0; mf < 4; mf++)
#pragma unroll
        for (int nf = 0; nf < 4; nf++)
#pragma unroll
            for (int q = 0; q < 4; q++) acc[mf][nf][q] = 0.f;

#pragma unroll
    for (int s = 0; s < 3; s++) {
        cpa16(Asw + s * 3072, Ab + s * 16);
        cpa16(Bsw + s * 3072, Bb + s * 16);
        CP_COMMIT();
    }

    const int frag_off = (i_ + ((g & 1) << 3)) * 24 + ((g >> 1) << 3);

    for (int kt = 0; kt < nk; kt++) {
        CP_WAIT2();
        __syncthreads();
        if (kt + 3 < nk) {
            const int st = (kt + 3) & 3;
            cpa16(Asw + st * 3072, Ab + (kt + 3) * 16);
            cpa16(Bsw + st * 3072, Bb + (kt + 3) * 16);
            CP_COMMIT();
        }
        const __nv_bfloat16* Ac = As + (kt & 3) * 3072;
        const __nv_bfloat16* Bc = Bs + (kt & 3) * 3072;
        uint32_t af[4][4], bf[2][4];
#pragma unroll
        for (int mf = 0; mf < 4; mf++)
            ldsm4b(af[mf], Ac + (wm + mf * 16) * 24 + frag_off);
#pragma unroll
        for (int p = 0; p < 2; p++)
            ldsm4b(bf[p], Bc + (wn + p * 16) * 24 + frag_off);
#pragma unroll
        for (int mf = 0; mf < 4; mf++)
#pragma unroll
            for (int nf = 0; nf < 4; nf++) {
                uint32_t bb[2] = { bf[nf >> 1][nf & 1], bf[nf >> 1][(nf & 1) + 2] };
                mma_bf16(acc[mf][nf], af[mf], bb);
            }
    }

#pragma unroll
    for (int mf = 0; mf < 4; mf++) {
#pragma unroll
        for (int nf = 0; nf < 4; nf++) {
            const int row = m0 + wm + mf * 16 + r;
            const int col = n0 + wn + nf * 8 + (cl << 1);
            *(float2*)(C + (size_t)row * N + col) =
                make_float2(acc[mf][nf][0], acc[mf][nf][1]);
            *(float2*)(C + (size_t)(row + 8) * N + col) =
                make_float2(acc[mf][nf][2], acc[mf][nf][3]);
        }
    }
}

// ---------------- conv weight transform (3 sets fused) ----------------
__global__ void wt_xform3(const float* __restrict__ cwq, const float* __restrict__ cwk,
                          const float* __restrict__ cwv,
                          uint32_t* __restrict__ wtq, uint32_t* __restrict__ wtk,
                          uint32_t* __restrict__ wtv)
{
    const int idx = blockIdx.x * 256 + threadIdx.x;
    if (idx >= 448 * 64) return;
    const float* cw = (blockIdx.y == 0) ? cwq : (blockIdx.y == 1) ? cwk : cwv;
    uint32_t* wt = (blockIdx.y == 0) ? wtq : (blockIdx.y == 1) ? wtk : wtv;
    const int kidx = idx >> 6, o = idx & 63;
    const int i = kidx & 63, k = kidx >> 6;
    wt[idx] = f2tf(cw[(o * 64 + i) * CONVC + k]);
}

// ---------------- conv1d as shifted GEMM on tensor cores (3 fused) --------
__global__ __launch_bounds__(256)
void conv_mma(const float* __restrict__ heads,
              const uint32_t* __restrict__ wtq, const uint32_t* __restrict__ wtk,
              const uint32_t* __restrict__ wtv,
              const float* __restrict__ cbq, const float* __restrict__ cbk,
              const float* __restrict__ cbv,
              float* __restrict__ oq, float* __restrict__ ok, float* __restrict__ ov)
{
    __shared__ uint32_t xs[134][68];   // [l - l0 + 3][i], tf32 bits
    __shared__ uint32_t bs[32][72];    // [ii][o]
    const int z = blockIdx.z;
    const int colbase = z * DMC;
    const uint32_t* wt = (z == 0) ? wtq : (z == 1) ? wtk : wtv;
    const float* cb = (z == 0) ? cbq : (z == 1) ? cbk : cbv;
    float* out = (z == 0) ? oq : (z == 1) ? ok : ov;

    const int t = threadIdx.x;
    const int warp = t >> 5, lane = t & 31;
    const int wm = (warp >> 1) * 32, wn = (warp & 1) * 32;
    const int r = lane >> 2, c = lane & 3;
    const int nb = blockIdx.y;
    const int n = nb >> 2, b = nb & 3;
    const int l0 = blockIdx.x << 7;

    for (int u = t; u < 134 * 16; u += 256) {
        const int row = u >> 4, i4 = (u & 15) << 2;
        const int gl = l0 + row - 3;
        float4 v = make_float4(0.f, 0.f, 0.f, 0.f);
        if (gl >= 0 && gl < QLENC)
            v = *(const float4*)(heads + (size_t)(gl * BSZC + b) * H3C +
                                 colbase + n * DHC + i4);
        xs[row][i4]     = f2tf(v.x);
        xs[row][i4 + 1] = f2tf(v.y);
        xs[row][i4 + 2] = f2tf(v.z);
        xs[row][i4 + 3] = f2tf(v.w);
    }

    float acc[2][4][4];
#pragma unroll
    for (int mf = 0; mf < 2; mf++)
#pragma unroll
        for (int nf = 0; nf < 4; nf++)
#pragma unroll
            for (int q = 0; q < 4; q++) acc[mf][nf][q] = 0.f;

    for (int chunk = 0; chunk < 14; chunk++) {
        const int k = chunk >> 1;
        const int ibase = (chunk & 1) << 5;
        __syncthreads();
        for (int u = t; u < 32 * 16; u += 256) {
            const int ii = u >> 4, o4 = (u & 15) << 2;
            *(uint4*)&bs[ii][o4] =
                *(const uint4*)(wt + ((size_t)(k * 64 + ibase + ii) << 6) + o4);
        }
        __syncthreads();

#pragma unroll
        for (int ks = 0; ks < 4; ks++) {
            const int kb = ks << 3;
            uint32_t af[2][4];
#pragma unroll
            for (int mf = 0; mf < 2; mf++) {
                const int m = wm + mf * 16 + r;
                af[mf][0] = xs[m + k][ibase + kb + c];
                af[mf][1] = xs[m + 8 + k][ibase + kb + c];
                af[mf][2] = xs[m + k][ibase + kb + c + 4];
                af[mf][3] = xs[m + 8 + k][ibase + kb + c + 4];
            }
            uint32_t bf[4][2];
#pragma unroll
            for (int nf = 0; nf < 4; nf++) {
                const int o = wn + nf * 8 + r;
                bf[nf][0] = bs[kb + c][o];
                bf[nf][1] = bs[kb + c + 4][o];
            }
#pragma unroll
            for (int mf = 0; mf < 2; mf++)
#pragma unroll
                for (int nf = 0; nf < 4; nf++)
                    mma_tf32(acc[mf][nf], af[mf], bf[nf]);
        }
    }

#pragma unroll
    for (int mf = 0; mf < 2; mf++) {
#pragma unroll
        for (int nf = 0; nf < 4; nf++) {
            const int gl = l0 + wm + mf * 16 + r;
            const int o = wn + nf * 8 + (c << 1);
            const float b0 = __ldg(cb + o), b1 = __ldg(cb + o + 1);
            float2* p0 = (float2*)(out + (size_t)((gl * BSZC + b) * NHC + n) * DHC + o);
            float2* p1 = (float2*)(out + (size_t)(((gl + 8) * BSZC + b) * NHC + n) * DHC + o);
            *p0 = make_float2(acc[mf][nf][0] + b0, acc[mf][nf][1] + b1);
            *p1 = make_float2(acc[mf][nf][2] + b0, acc[mf][nf][3] + b1);
        }
    }
}

// ---------------- fused rel-attention with tensor-core MMA -----------------
// score[i,j] = (q_i+rwb)·k_j + (q_i+rrb)·rk[1023-(i-j)]   (j<=i)
// j-tiles processed DESCENDING; T[i][drel] kept in 128-wide ring buffer,
// only the 64 new drel columns computed per tile.
#define ATT_SMEM (34688 * 4)
__global__ __launch_bounds__(256)
void attn_mma(const float* __restrict__ qh, const float* __restrict__ kh,
              const float* __restrict__ vh, const float* __restrict__ rk,
              const float* __restrict__ rwb, const float* __restrict__ rrb,
              float* __restrict__ attv)
{
    extern __shared__ float sh[];
    float* qw_s   = sh;            // [64][68]  (i, d)
    float* qr_s   = sh + 4352;     // [64][68]
    float* k_s    = sh + 8704;     // [64][68]  (j, d)
    float* v_s    = sh + 13056;    // [64][68]  (d, j)  transposed
    float* s_s    = sh + 17408;    // [64][68]  scores, then P
    float* rk_s   = sh + 21760;    // [64][68]  (x, d), new drel block
    float* t_s    = sh + 26112;    // [64][132] ring over drel&127
    float* corr_s = sh + 34560;    // [64]
    float* linv_s = sh + 34624;    // [64]

    const int i0 = blockIdx.x << 6, b = blockIdx.y, n = blockIdx.z;
    const int t = threadIdx.x, warp = t >> 5, lane = t & 31;
    const int r = lane >> 2, cl = lane & 3, g = lane >> 3, i_ = lane & 7;
    const int wi = warp >> 1, wj = warp & 1;
    const int ty = t >> 4, tx = t & 15;

    // load Q tiles with biases
    for (int u = t; u < 1024; u += 256) {
        const int il = u >> 4, d4 = (u & 15) << 2;
        const float4 qv = *(const float4*)(qh +
            ((size_t)((i0 + il) * BSZC + b) * NHC + n) * DHC + d4);
        const float4 wv = *(const float4*)(rwb + n * DHC + d4);
        const float4 rv = *(const float4*)(rrb + n * DHC + d4);
        *(float4*)&qw_s[il * 68 + d4] =
            make_float4(qv.x + wv.x, qv.y + wv.y, qv.z + wv.z, qv.w + wv.w);
        *(float4*)&qr_s[il * 68 + d4] =
            make_float4(qv.x + rv.x, qv.y + rv.y, qv.z + rv.z, qv.w + rv.w);
    }

    float oacc[4][4];
#pragma unroll
    for (int nf = 0; nf < 4; nf++)
#pragma unroll
        for (int q = 0; q < 4; q++) oacc[nf][q] = 0.f;
    float m_r[4], l_r[4];
#pragma unroll
    for (int a = 0; a < 4; a++) { m_r[a] = -1e30f; l_r[a] = 0.f; }

    const int acoff = (g >> 1) << 2, aroff = ((g & 1) << 3) + i_;
    const int bcoff = (g & 1) << 2,  broff = ((g >> 1) << 3) + i_;

    for (int j0 = i0; j0 >= 0; j0 -= 64) {
        const int base = i0 - j0;          // multiple of 64
        const int ringoff = base & 127;    // 0 or 64
        __syncthreads();
        // K, V(transposed)
        for (int u = t; u < 1024; u += 256) {
            const int jl = u >> 4, d4 = (u & 15) << 2;
            const size_t gi = ((size_t)((j0 + jl) * BSZC + b) * NHC + n) * DHC + d4;
            *(float4*)&k_s[jl * 68 + d4] = *(const float4*)(kh + gi);
            const float4 vv = *(const float4*)(vh + gi);
            v_s[(d4 + 0) * 68 + jl] = vv.x;
            v_s[(d4 + 1) * 68 + jl] = vv.y;
            v_s[(d4 + 2) * 68 + jl] = vv.z;
            v_s[(d4 + 3) * 68 + jl] = vv.w;
        }
        // new rel block: drel in [base, base+63]  (always in-range)
        for (int u = t; u < 1024; u += 256) {
            const int x = u >> 4, d4 = (u & 15) << 2;
            const int drel = base + x;
            *(float4*)&rk_s[x * 68 + d4] =
                *(const float4*)(rk + (size_t)(QLENC - 1 - drel) * DMC +
                                 n * DHC + d4);
        }
        __syncthreads();

        // S = Qw K^T  (warp: rows wi*16, cols wj*32)
        {
            float cf[4][4];
#pragma unroll
            for (int nf = 0; nf < 4; nf++)
#pragma unroll
                for (int q = 0; q < 4; q++) cf[nf][q] = 0.f;
            const float* arow = qw_s + (wi * 16 + aroff) * 68 + acoff;
            const float* brow = k_s + (wj * 32 + broff) * 68 + bcoff;
#pragma unroll
            for (int ks = 0; ks < 8; ks++) {
                uint32_t a4[4], b4[2][4];
                ldsm4(a4, arow + ks * 8);
                ldsm4(b4[0], brow + ks * 8);
                ldsm4(b4[1], brow + 16 * 68 + ks * 8);
#pragma unroll
                for (int nf = 0; nf < 4; nf++) {
                    uint32_t bb[2] = { b4[nf >> 1][(nf & 1) * 2],
                                       b4[nf >> 1][(nf & 1) * 2 + 1] };
                    mma_tf32(cf[nf], a4, bb);
                }
            }
            const int sr = wi * 16 + r;
#pragma unroll
            for (int nf = 0; nf < 4; nf++) {
                const int col = wj * 32 + nf * 8 + (cl << 1);
                *(float2*)&s_s[sr * 68 + col]       = make_float2(cf[nf][0], cf[nf][1]);
                *(float2*)&s_s[(sr + 8) * 68 + col] = make_float2(cf[nf][2], cf[nf][3]);
            }
        }
        // T(new block) = Qr Rks^T  (warp: rows wi*16, cols(x) wj*32)
        {
            float cf[4][4];
#pragma unroll
            for (int nf = 0; nf < 4; nf++)
#pragma unroll
                for (int q = 0; q < 4; q++) cf[nf][q] = 0.f;
            const float* arow = qr_s + (wi * 16 + aroff) * 68 + acoff;
            const float* brow = rk_s + (wj * 32 + broff) * 68 + bcoff;
#pragma unroll
            for (int ks = 0; ks < 8; ks++) {
                uint32_t a4[4], b4[2][4];
                ldsm4(a4, arow + ks * 8);
                ldsm4(b4[0], brow + ks * 8);
                ldsm4(b4[1], brow + 16 * 68 + ks * 8);
#pragma unroll
                for (int nf = 0; nf < 4; nf++) {
                    uint32_t bb[2] = { b4[nf >> 1][(nf & 1) * 2],
                                       b4[nf >> 1][(nf & 1) * 2 + 1] };
                    mma_tf32(cf[nf], a4, bb);
                }
            }
            const int sr = wi * 16 + r;
#pragma unroll
            for (int nf = 0; nf < 4; nf++) {
                const int col = ringoff + wj * 32 + nf * 8 + (cl << 1);
                *(float2*)&t_s[sr * 132 + col]       = make_float2(cf[nf][0], cf[nf][1]);
                *(float2*)&t_s[(sr + 8) * 132 + col] = make_float2(cf[nf][2], cf[nf][3]);
            }
        }
        __syncthreads();

        // softmax (thread owns rows il = 4ty+a, cols 4tx..4tx+3)
#pragma unroll
        for (int a = 0; a < 4; a++) {
            const int il = (ty << 2) + a;
            const int gi = i0 + il;
            const float4 sv = *(const float4*)&s_s[il * 68 + (tx << 2)];
            float s4[4] = {sv.x, sv.y, sv.z, sv.w};
            float mx = -1e30f;
#pragma unroll
            for (int c = 0; c < 4; c++) {
                const int jl = (tx << 2) + c;
                const float tv = t_s[il * 132 + ((base + il - jl) & 127)];
                float v = (s4[c] + tv) * SCALEC;
                if (j0 + jl > gi) v = NEGC;
                s4[c] = v;
                mx = fmaxf(mx, v);
            }
#pragma unroll
            for (int off = 1; off < 16; off <<= 1)
                mx = fmaxf(mx, __shfl_xor_sync(0xffffffffu, mx, off, 16));
            const float mnew = fmaxf(m_r[a], mx);
            const float corr = __expf(m_r[a] - mnew);
            float psum = 0.f;
#pragma unroll
            for (int c = 0; c < 4; c++) {
                s4[c] = __expf(s4[c] - mnew);
                psum += s4[c];
            }
#pragma unroll
            for (int off = 1; off < 16; off <<= 1)
                psum += __shfl_xor_sync(0xffffffffu, psum, off, 16);
            l_r[a] = l_r[a] * corr + psum;
            m_r[a] = mnew;
            if (tx == 0) corr_s[il] = corr;
            *(float4*)&s_s[il * 68 + (tx << 2)] =
                make_float4(s4[0], s4[1], s4[2], s4[3]);
        }
        __syncthreads();

        // PV: O += P V   (warp: rows wi*16, cols(d) wj*32)
        {
            const float c0 = corr_s[wi * 16 + r], c1 = corr_s[wi * 16 + 8 + r];
#pragma unroll
            for (int nf = 0; nf < 4; nf++) {
                oacc[nf][0] *= c0; oacc[nf][1] *= c0;
                oacc[nf][2] *= c1; oacc[nf][3] *= c1;
            }
            const float* arow = s_s + (wi * 16 + aroff) * 68 + acoff;
            const float* brow = v_s + (wj * 32 + broff) * 68 + bcoff;
#pragma unroll
            for (int ks = 0; ks < 8; ks++) {
                uint32_t a4[4], b4[2][4];
                ldsm4(a4, arow + ks * 8);
                ldsm4(b4[0], brow + ks * 8);
                ldsm4(b4[1], brow + 16 * 68 + ks * 8);
#pragma unroll
                for (int nf = 0; nf < 4; nf++) {
                    uint32_t bb[2] = { b4[nf >> 1][(nf & 1) * 2],
                                       b4[nf >> 1][(nf & 1) * 2 + 1] };
                    mma_tf32(oacc[nf], a4, bb);
                }
            }
        }
    }

    if (tx == 0) {
#pragma unroll
        for (int a = 0; a < 4; a++) linv_s[(ty << 2) + a] = 1.f / l_r[a];
    }
    __syncthreads();
    {
        const int ir0 = i0 + wi * 16 + r;
        const float li0 = linv_s[wi * 16 + r], li1 = linv_s[wi * 16 + 8 + r];
#pragma unroll
        for (int nf = 0; nf < 4; nf++) {
            const int d = wj * 32 + nf * 8 + (cl << 1);
            *(float2*)(attv + ((size_t)(ir0 * BSZC + b) * NHC + n) * DHC + d) =
                make_float2(oacc[nf][0] * li0, oacc[nf][1] * li0);
            *(float2*)(attv + ((size_t)((ir0 + 8) * BSZC + b) * NHC + n) * DHC + d) =
                make_float2(oacc[nf][2] * li1, oacc[nf][3] * li1);
        }
    }
}

// ---------------- residual + LayerNorm ----------------
__global__ __launch_bounds__(256)
void ln_kernel(const float* __restrict__ w, const float* __restrict__ ao,
               const float* __restrict__ gamma, const float* __restrict__ beta,
               float* __restrict__ out)
{
    __shared__ float red[16];
    const int row = blockIdx.x, t = threadIdx.x;
    const size_t base = (size_t)row * DMC + t * 4;
    const float4 wv = *(const float4*)(w + base);
    const float4 av = *(const float4*)(ao + base);
    float x[4] = {wv.x + av.x, wv.y + av.y, wv.z + av.z, wv.w + av.w};
    float s1 = x[0] + x[1] + x[2] + x[3];
    float s2 = x[0]*x[0] + x[1]*x[1] + x[2]*x[2] + x[3]*x[3];
#pragma unroll
    for (int off = 16; off; off >>= 1) {
        s1 += __shfl_xor_sync(0xffffffffu, s1, off);
        s2 += __shfl_xor_sync(0xffffffffu, s2, off);
    }
    if ((t & 31) == 0) { red[t >> 5] = s1; red[8 + (t >> 5)] = s2; }
    __syncthreads();
    float ts1 = 0.f, ts2 = 0.f;
#pragma unroll
    for (int i = 0; i < 8; i++) { ts1 += red[i]; ts2 += red[8 + i]; }
    const float mu   = ts1 * (1.f / DMC);
    const float var  = ts2 * (1.f / DMC) - mu * mu;
    const float rstd = rsqrtf(var + 1e-5f);
    const float4 gv = *(const float4*)(gamma + t * 4);
    const float4 bv = *(const float4*)(beta + t * 4);
    float4 o;
    o.x = (x[0] - mu) * rstd * gv.x + bv.x;
    o.y = (x[1] - mu) * rstd * gv.y + bv.y;
    o.z = (x[2] - mu) * rstd * gv.z + bv.z;
    o.w = (x[3] - mu) * rstd * gv.w + bv.w;
    *(float4*)(out + base) = o;
}

// ---------------- launcher ----------------
extern "C" void kernel_launch(void* const* d_in, const int* in_sizes, int n_in,
                              void* d_out, int out_size)
{
    (void)in_sizes; (void)n_in; (void)out_size;
    const float* w    = (const float*)d_in[0];
    const float* r    = (const float*)d_in[1];
    const float* rwb  = (const float*)d_in[2];
    const float* rrb  = (const float*)d_in[3];
    const float* Wqkv = (const float*)d_in[4];
    const float* Wr   = (const float*)d_in[5];
    const float* Wo   = (const float*)d_in[6];
    const float* cwq  = (const float*)d_in[7];
    const float* cbq  = (const float*)d_in[8];
    const float* cwk  = (const float*)d_in[9];
    const float* cbk  = (const float*)d_in[10];
    const float* cwv  = (const float*)d_in[11];
    const float* cbv  = (const float*)d_in[12];
    const float* gam  = (const float*)d_in[13];
    const float* bet  = (const float*)d_in[14];

    float *heads, *qh, *kh, *vh, *rkb, *attv, *aout;
    uint32_t *wtq, *wtk, *wtv;
    __nv_bfloat16 *bw, *bqkv, *br, *bwr, *bwo, *battv;
    cudaGetSymbolAddress((void**)&heads, g_heads);
    cudaGetSymbolAddress((void**)&qh,    g_qh);
    cudaGetSymbolAddress((void**)&kh,    g_kh);
    cudaGetSymbolAddress((void**)&vh,    g_vh);
    cudaGetSymbolAddress((void**)&rkb,   g_rk);
    cudaGetSymbolAddress((void**)&attv,  g_attv);
    cudaGetSymbolAddress((void**)&aout,  g_aout);
    cudaGetSymbolAddress((void**)&wtq,   g_wtq);
    cudaGetSymbolAddress((void**)&wtk,   g_wtk);
    cudaGetSymbolAddress((void**)&wtv,   g_wtv);
    cudaGetSymbolAddress((void**)&bw,    g_bw);
    cudaGetSymbolAddress((void**)&bqkv,  g_bqkv);
    cudaGetSymbolAddress((void**)&br,    g_br);
    cudaGetSymbolAddress((void**)&bwr,   g_bwr);
    cudaGetSymbolAddress((void**)&bwo,   g_bwo);
    cudaGetSymbolAddress((void**)&battv, g_battv);

    cudaFuncSetAttribute(bgemm,
                         cudaFuncAttributeMaxDynamicSharedMemorySize, BG_SMEM);
    cudaFuncSetAttribute(attn_mma,
                         cudaFuncAttributeMaxDynamicSharedMemorySize, ATT_SMEM);

    // 0. converts + conv weight transforms
    cvt5<<<10240, 256>>>(w, Wqkv, r, Wr, Wo, bw, bqkv, br, bwr, bwo);
    wt_xform3<<<dim3(112, 3), 256>>>(cwq, cwk, cwv, wtq, wtk, wtv);
    // 1. heads = w @ W_qkv^T   [4096 x 3072]
    bgemm<<<dim3(H3C / 128, ROWSC / 128), 256, BG_SMEM>>>(
        bw, bqkv, heads, ROWSC, H3C, DMC);
    // 2. r_head_k = r @ W_r^T  [1024 x 1024]
    bgemm<<<dim3(DMC / 128, QLENC / 128), 256, BG_SMEM>>>(
        br, bwr, rkb, QLENC, DMC, DMC);
    // 3. convs (tensor-core shifted GEMM, 3 fused)
    conv_mma<<<dim3(8, 64, 3), 256>>>(heads, wtq, wtk, wtv,
                                      cbq, cbk, cbv, qh, kh, vh);
    // 4. fused rel-attention on tensor cores
    attn_mma<<<dim3(16, 4, 16), 256, ATT_SMEM>>>(qh, kh, vh, rkb, rwb, rrb, attv);
    // 5. out projection
    cvt1<<<4096, 256>>>(attv, battv);
    bgemm<<<dim3(DMC / 128, ROWSC / 128), 256, BG_SMEM>>>(
        battv, bwo, aout, ROWSC, DMC, DMC);
    // 6. residual + LN
    ln_kernel<<<ROWSC, 256>>>(w, aout, gam, bet, (float*)d_out);
}

// round 5
// speedup vs baseline: 6.0776x; 1.4439x over previous
#include <cuda_runtime.h>
#include <cuda_bf16.h>
#include <cstdint>

#define QLENC 1024
#define BSZC  4
#define NHC   16
#define DHC   64
#define DMC   1024
#define H3C   3072
#define ROWSC 4096   // QLEN*BSZ
#define CONVC 7
#define SCALEC 0.125f
#define NEGC  -1e30f

// ---------------- scratch (no allocation allowed) ----------------
__device__ __nv_bfloat16 g_bheads[(size_t)ROWSC * H3C]; // [row][3*N*D]
__device__ __nv_bfloat16 g_bqh[(size_t)ROWSC * DMC];    // [l][b][n][d]
__device__ __nv_bfloat16 g_bkh[(size_t)ROWSC * DMC];
__device__ __nv_bfloat16 g_bvh[(size_t)ROWSC * DMC];
__device__ __nv_bfloat16 g_brk[(size_t)QLENC * DMC];    // [rho][n][d]
__device__ __nv_bfloat16 g_battv[(size_t)ROWSC * DMC];  // [row][n*64+d]
__device__ float g_aout[(size_t)ROWSC * DMC];
// bf16 operand copies
__device__ __nv_bfloat16 g_bw[(size_t)ROWSC * DMC];
__device__ __nv_bfloat16 g_bqkv[(size_t)H3C * DMC];
__device__ __nv_bfloat16 g_br[(size_t)QLENC * DMC];
__device__ __nv_bfloat16 g_bwr[(size_t)DMC * DMC];
__device__ __nv_bfloat16 g_bwo[(size_t)DMC * DMC];
// conv weights, [o][k*64+i] bf16
__device__ __nv_bfloat16 g_wtq[64 * 448];
__device__ __nv_bfloat16 g_wtk[64 * 448];
__device__ __nv_bfloat16 g_wtv[64 * 448];

// ---------------- helpers ----------------
__device__ __forceinline__ void mma_bf16(float c[4], const uint32_t a[4],
                                         const uint32_t b[2]) {
    asm volatile(
        "mma.sync.aligned.m16n8k16.row.col.f32.bf16.bf16.f32 "
        "{%0,%1,%2,%3}, {%4,%5,%6,%7}, {%8,%9}, {%0,%1,%2,%3};"
        : "+f"(c[0]), "+f"(c[1]), "+f"(c[2]), "+f"(c[3])
        : "r"(a[0]), "r"(a[1]), "r"(a[2]), "r"(a[3]), "r"(b[0]), "r"(b[1]));
}

__device__ __forceinline__ void ldsm4b(uint32_t d[4], const __nv_bfloat16* p) {
    uint32_t a = (uint32_t)__cvta_generic_to_shared(p);
    asm volatile("ldmatrix.sync.aligned.m8n8.x4.shared.b16 {%0,%1,%2,%3}, [%4];"
                 : "=r"(d[0]), "=r"(d[1]), "=r"(d[2]), "=r"(d[3]) : "r"(a));
}

__device__ __forceinline__ void cpa16(const void* s, const void* g) {
    uint32_t sa = (uint32_t)__cvta_generic_to_shared(s);
    asm volatile("cp.async.cg.shared.global [%0], [%1], 16;" :: "r"(sa), "l"(g));
}
#define CP_COMMIT() asm volatile("cp.async.commit_group;")
#define CP_WAIT2()  asm volatile("cp.async.wait_group 2;")

// ---------------- fp32 -> bf16 converts (fused) ----------------
__global__ __launch_bounds__(256)
void cvt5(const float* __restrict__ w, const float* __restrict__ Wqkv,
          const float* __restrict__ r, const float* __restrict__ Wr,
          const float* __restrict__ Wo,
          __nv_bfloat16* __restrict__ ow, __nv_bfloat16* __restrict__ oq,
          __nv_bfloat16* __restrict__ orr, __nv_bfloat16* __restrict__ owr,
          __nv_bfloat16* __restrict__ owo)
{
    int idx = blockIdx.x * 256 + threadIdx.x;   // float4 index
    const float* src; __nv_bfloat16* dst;
    if (idx < 1048576)      { src = w;    dst = ow; }
    else if (idx < 1835008) { src = Wqkv; dst = oq;  idx -= 1048576; }
    else if (idx < 2097152) { src = r;    dst = orr; idx -= 1835008; }
    else if (idx < 2359296) { src = Wr;   dst = owr; idx -= 2097152; }
    else                    { src = Wo;   dst = owo; idx -= 2359296; }
    const float4 v = *(const float4*)(src + (size_t)idx * 4);
    __nv_bfloat162* d2 = (__nv_bfloat162*)(dst + (size_t)idx * 4);
    d2[0] = __floats2bfloat162_rn(v.x, v.y);
    d2[1] = __floats2bfloat162_rn(v.z, v.w);
}

// ---------------- BF16 GEMM: C[M,N] = A[M,K] * B[N,K]^T -------------------
#define BG_SMEM (2 * 4 * 128 * 24 * 2)   // 49152 bytes
template<bool BOUT>
__global__ __launch_bounds__(256, 2)
void bgemm(const __nv_bfloat16* __restrict__ A, const __nv_bfloat16* __restrict__ B,
           void* __restrict__ Cv, int M, int N, int K)
{
    extern __shared__ __nv_bfloat16 shb[];
    __nv_bfloat16* As = shb;                 // [4][128][24]
    __nv_bfloat16* Bs = shb + 4 * 128 * 24;
    const int t = threadIdx.x, warp = t >> 5, lane = t & 31;
    const int r = lane >> 2, cl = lane & 3, g = lane >> 3, i_ = lane & 7;
    const int wm = (warp >> 2) * 64, wn = (warp & 3) * 32;
    const int m0 = blockIdx.y << 7, n0 = blockIdx.x << 7;
    const int srow = t >> 1, sc = (t & 1) << 3;

    const __nv_bfloat16* Ab = A + (size_t)(m0 + srow) * K + sc;
    const __nv_bfloat16* Bb = B + (size_t)(n0 + srow) * K + sc;
    __nv_bfloat16* Asw = As + srow * 24 + sc;
    __nv_bfloat16* Bsw = Bs + srow * 24 + sc;
    const int nk = K >> 4;

    float acc[4][4][4];
#pragma unroll
    for (int mf = 0; mf < 4; mf++)
#pragma unroll
        for (int nf = 0; nf < 4; nf++)
#pragma unroll
            for (int q = 0; q < 4; q++) acc[mf][nf][q] = 0.f;

#pragma unroll
    for (int s = 0; s < 3; s++) {
        cpa16(Asw + s * 3072, Ab + s * 16);
        cpa16(Bsw + s * 3072, Bb + s * 16);
        CP_COMMIT();
    }

    const int frag_off = (i_ + ((g & 1) << 3)) * 24 + ((g >> 1) << 3);

    for (int kt = 0; kt < nk; kt++) {
        CP_WAIT2();
        __syncthreads();
        if (kt + 3 < nk) {
            const int st = (kt + 3) & 3;
            cpa16(Asw + st * 3072, Ab + (kt + 3) * 16);
            cpa16(Bsw + st * 3072, Bb + (kt + 3) * 16);
            CP_COMMIT();
        }
        const __nv_bfloat16* Ac = As + (kt & 3) * 3072;
        const __nv_bfloat16* Bc = Bs + (kt & 3) * 3072;
        uint32_t af[4][4], bf[2][4];
#pragma unroll
        for (int mf = 0; mf < 4; mf++)
            ldsm4b(af[mf], Ac + (wm + mf * 16) * 24 + frag_off);
#pragma unroll
        for (int p = 0; p < 2; p++)
            ldsm4b(bf[p], Bc + (wn + p * 16) * 24 + frag_off);
#pragma unroll
        for (int mf = 0; mf < 4; mf++)
#pragma unroll
            for (int nf = 0; nf < 4; nf++) {
                uint32_t bb[2] = { bf[nf >> 1][nf & 1], bf[nf >> 1][(nf & 1) + 2] };
                mma_bf16(acc[mf][nf], af[mf], bb);
            }
    }

#pragma unroll
    for (int mf = 0; mf < 4; mf++) {
#pragma unroll
        for (int nf = 0; nf < 4; nf++) {
            const int row = m0 + wm + mf * 16 + r;
            const int col = n0 + wn + nf * 8 + (cl << 1);
            if (BOUT) {
                __nv_bfloat16* C = (__nv_bfloat16*)Cv;
                *(__nv_bfloat162*)(C + (size_t)row * N + col) =
                    __floats2bfloat162_rn(acc[mf][nf][0], acc[mf][nf][1]);
                *(__nv_bfloat162*)(C + (size_t)(row + 8) * N + col) =
                    __floats2bfloat162_rn(acc[mf][nf][2], acc[mf][nf][3]);
            } else {
                float* C = (float*)Cv;
                *(float2*)(C + (size_t)row * N + col) =
                    make_float2(acc[mf][nf][0], acc[mf][nf][1]);
                *(float2*)(C + (size_t)(row + 8) * N + col) =
                    make_float2(acc[mf][nf][2], acc[mf][nf][3]);
            }
        }
    }
}

// ---------------- conv weight transform (3 sets fused) ----------------
// cw[O][I][K] -> wt[o][k*64+i] bf16
__global__ void wt_xform3(const float* __restrict__ cwq, const float* __restrict__ cwk,
                          const float* __restrict__ cwv,
                          __nv_bfloat16* __restrict__ wtq, __nv_bfloat16* __restrict__ wtk,
                          __nv_bfloat16* __restrict__ wtv)
{
    const int idx = blockIdx.x * 256 + threadIdx.x;
    if (idx >= 64 * 448) return;
    const float* cw = (blockIdx.y == 0) ? cwq : (blockIdx.y == 1) ? cwk : cwv;
    __nv_bfloat16* wt = (blockIdx.y == 0) ? wtq : (blockIdx.y == 1) ? wtk : wtv;
    const int o = idx / 448, kidx = idx % 448;
    const int k = kidx >> 6, i = kidx & 63;
    wt[idx] = __float2bfloat16(cw[(o * 64 + i) * CONVC + k]);
}

// ---------------- conv1d as shifted GEMM, bf16, weights resident ----------
// y[l][o] = sum_{i,k} x[l+k-3][i] * cw[o][i][k] + b[o], per (n,b,qkv).
#define CONV_SMEM (134 * 72 * 2 + 64 * 456 * 2)
__global__ __launch_bounds__(256)
void conv_mma(const __nv_bfloat16* __restrict__ heads,
              const __nv_bfloat16* __restrict__ wtq, const __nv_bfloat16* __restrict__ wtk,
              const __nv_bfloat16* __restrict__ wtv,
              const float* __restrict__ cbq, const float* __restrict__ cbk,
              const float* __restrict__ cbv,
              __nv_bfloat16* __restrict__ oq, __nv_bfloat16* __restrict__ ok,
              __nv_bfloat16* __restrict__ ov)
{
    extern __shared__ __nv_bfloat16 shc[];
    __nv_bfloat16* xs = shc;              // [134][72]  (l+3, i)
    __nv_bfloat16* ws = shc + 134 * 72;   // [64][456]  (o, k*64+i)
    const int z = blockIdx.z;
    const int colbase = z * DMC;
    const __nv_bfloat16* wt = (z == 0) ? wtq : (z == 1) ? wtk : wtv;
    const float* cb = (z == 0) ? cbq : (z == 1) ? cbk : cbv;
    __nv_bfloat16* out = (z == 0) ? oq : (z == 1) ? ok : ov;

    const int t = threadIdx.x;
    const int warp = t >> 5, lane = t & 31;
    const int r = lane >> 2, cl = lane & 3, g = lane >> 3, i_ = lane & 7;
    const int wm = (warp >> 1) * 32, wn = (warp & 1) * 32;
    const int nb = blockIdx.y;
    const int n = nb >> 2, b = nb & 3;
    const int l0 = blockIdx.x << 7;

    // x tile with halo (zero-padded), 8 bf16 per unit
    for (int u = t; u < 134 * 8; u += 256) {
        const int row = u >> 3, i8 = (u & 7) << 3;
        const int gl = l0 + row - 3;
        uint4 v = make_uint4(0, 0, 0, 0);
        if (gl >= 0 && gl < QLENC)
            v = *(const uint4*)(heads + (size_t)(gl * BSZC + b) * H3C +
                                colbase + n * DHC + i8);
        *(uint4*)(xs + row * 72 + i8) = v;
    }
    // weights resident: 64 x 448
    for (int u = t; u < 64 * 56; u += 256) {
        const int o = u / 56, grp = u % 56;
        *(uint4*)(ws + o * 456 + grp * 8) = *(const uint4*)(wt + o * 448 + grp * 8);
    }
    __syncthreads();

    float acc[2][4][4];
#pragma unroll
    for (int mf = 0; mf < 2; mf++)
#pragma unroll
        for (int nf = 0; nf < 4; nf++)
#pragma unroll
            for (int q = 0; q < 4; q++) acc[mf][nf][q] = 0.f;

    const int arow_off = i_ + ((g & 1) << 3);
    const int acol_off = (g >> 1) << 3;

#pragma unroll 4
    for (int kc = 0; kc < 28; kc++) {
        const int k = kc >> 2;              // conv tap 0..6
        const int ibase = (kc & 3) << 4;    // i chunk base 0..48
        uint32_t af[2][4], bf[2][4];
#pragma unroll
        for (int mf = 0; mf < 2; mf++)
            ldsm4b(af[mf], xs + (wm + mf * 16 + k + arow_off) * 72 + ibase + acol_off);
#pragma unroll
        for (int p = 0; p < 2; p++)
            ldsm4b(bf[p], ws + (wn + p * 16 + arow_off) * 456 + kc * 16 + acol_off);
#pragma unroll
        for (int mf = 0; mf < 2; mf++)
#pragma unroll
            for (int nf = 0; nf < 4; nf++) {
                uint32_t bb[2] = { bf[nf >> 1][nf & 1], bf[nf >> 1][(nf & 1) + 2] };
                mma_bf16(acc[mf][nf], af[mf], bb);
            }
    }

#pragma unroll
    for (int mf = 0; mf < 2; mf++) {
#pragma unroll
        for (int nf = 0; nf < 4; nf++) {
            const int gl = l0 + wm + mf * 16 + r;
            const int o = wn + nf * 8 + (cl << 1);
            const float b0 = __ldg(cb + o), b1 = __ldg(cb + o + 1);
            *(__nv_bfloat162*)(out + (size_t)((gl * BSZC + b) * NHC + n) * DHC + o) =
                __floats2bfloat162_rn(acc[mf][nf][0] + b0, acc[mf][nf][1] + b1);
            *(__nv_bfloat162*)(out + (size_t)(((gl + 8) * BSZC + b) * NHC + n) * DHC + o) =
                __floats2bfloat162_rn(acc[mf][nf][2] + b0, acc[mf][nf][3] + b1);
        }
    }
}

// ---------------- fused rel-attention, bf16 MMA ----------------------------
// score[i,j] = (q_i+rwb)·k_j + (q_i+rrb)·rk[1023-(i-j)]   (j<=i)
// j-tiles DESCENDING; T ring buffer over drel&127, 64 new cols per tile.
#define ATT_SMEM (6 * 64 * 72 * 2 + (64 * 68 + 64 * 132 + 128) * 4)
__global__ __launch_bounds__(256)
void attn_mma(const __nv_bfloat16* __restrict__ qh, const __nv_bfloat16* __restrict__ kh,
              const __nv_bfloat16* __restrict__ vh, const __nv_bfloat16* __restrict__ rk,
              const float* __restrict__ rwb, const float* __restrict__ rrb,
              __nv_bfloat16* __restrict__ attv)
{
    extern __shared__ char shraw[];
    __nv_bfloat16* qw_s = (__nv_bfloat16*)shraw;            // [64][72] (i,d)
    __nv_bfloat16* qr_s = qw_s + 64 * 72;
    __nv_bfloat16* k_s  = qr_s + 64 * 72;                   // [64][72] (j,d)
    __nv_bfloat16* v_s  = k_s  + 64 * 72;                   // [64][72] (d,j)
    __nv_bfloat16* rk_s = v_s  + 64 * 72;                   // [64][72] (x,d)
    __nv_bfloat16* p_s  = rk_s + 64 * 72;                   // [64][72] (i,j)
    float* s_s    = (float*)(p_s + 64 * 72);                // [64][68]
    float* t_s    = s_s + 64 * 68;                          // [64][132] ring
    float* corr_s = t_s + 64 * 132;                         // [64]
    float* linv_s = corr_s + 64;                            // [64]

    const int i0 = blockIdx.x << 6, b = blockIdx.y, n = blockIdx.z;
    const int t = threadIdx.x, warp = t >> 5, lane = t & 31;
    const int r = lane >> 2, cl = lane & 3, g = lane >> 3, i_ = lane & 7;
    const int wi = warp >> 1, wj = warp & 1;
    const int ty = t >> 4, tx = t & 15;

    // Q tiles with biases (fp32 add, round to bf16)
    for (int u = t; u < 512; u += 256) {
        const int il = u >> 3, d8 = (u & 7) << 3;
        const uint4 qv = *(const uint4*)(qh +
            ((size_t)((i0 + il) * BSZC + b) * NHC + n) * DHC + d8);
        const __nv_bfloat162* q2 = (const __nv_bfloat162*)&qv;
        const float4 wv0 = *(const float4*)(rwb + n * DHC + d8);
        const float4 wv1 = *(const float4*)(rwb + n * DHC + d8 + 4);
        const float4 rv0 = *(const float4*)(rrb + n * DHC + d8);
        const float4 rv1 = *(const float4*)(rrb + n * DHC + d8 + 4);
        float qf[8];
#pragma unroll
        for (int q = 0; q < 4; q++) {
            float2 f = __bfloat1622float2(q2[q]);
            qf[2 * q] = f.x; qf[2 * q + 1] = f.y;
        }
        __nv_bfloat162* dw = (__nv_bfloat162*)(qw_s + il * 72 + d8);
        __nv_bfloat162* dr = (__nv_bfloat162*)(qr_s + il * 72 + d8);
        dw[0] = __floats2bfloat162_rn(qf[0] + wv0.x, qf[1] + wv0.y);
        dw[1] = __floats2bfloat162_rn(qf[2] + wv0.z, qf[3] + wv0.w);
        dw[2] = __floats2bfloat162_rn(qf[4] + wv1.x, qf[5] + wv1.y);
        dw[3] = __floats2bfloat162_rn(qf[6] + wv1.z, qf[7] + wv1.w);
        dr[0] = __floats2bfloat162_rn(qf[0] + rv0.x, qf[1] + rv0.y);
        dr[1] = __floats2bfloat162_rn(qf[2] + rv0.z, qf[3] + rv0.w);
        dr[2] = __floats2bfloat162_rn(qf[4] + rv1.x, qf[5] + rv1.y);
        dr[3] = __floats2bfloat162_rn(qf[6] + rv1.z, qf[7] + rv1.w);
    }

    float oacc[4][4];
#pragma unroll
    for (int nf = 0; nf < 4; nf++)
#pragma unroll
        for (int q = 0; q < 4; q++) oacc[nf][q] = 0.f;
    float m_r[4], l_r[4];
#pragma unroll
    for (int a = 0; a < 4; a++) { m_r[a] = -1e30f; l_r[a] = 0.f; }

    const int arow_off = i_ + ((g & 1) << 3);
    const int acol_off = (g >> 1) << 3;

    for (int j0 = i0; j0 >= 0; j0 -= 64) {
        const int base = i0 - j0;
        const int ringoff = base & 127;
        __syncthreads();
        // K, V(transposed), rk
        for (int u = t; u < 512; u += 256) {
            const int jl = u >> 3, d8 = (u & 7) << 3;
            const size_t gi = ((size_t)((j0 + jl) * BSZC + b) * NHC + n) * DHC + d8;
            *(uint4*)(k_s + jl * 72 + d8) = *(const uint4*)(kh + gi);
            const uint4 vv = *(const uint4*)(vh + gi);
            const __nv_bfloat16* v8 = (const __nv_bfloat16*)&vv;
#pragma unroll
            for (int q = 0; q < 8; q++)
                v_s[(d8 + q) * 72 + jl] = v8[q];
            const int drel = base + jl;
            *(uint4*)(rk_s + jl * 72 + d8) =
                *(const uint4*)(rk + (size_t)(QLENC - 1 - drel) * DMC + n * DHC + d8);
        }
        __syncthreads();

        // S = Qw K^T  (warp rows wi*16, cols wj*32)
        {
            float cf[4][4];
#pragma unroll
            for (int nf = 0; nf < 4; nf++)
#pragma unroll
                for (int q = 0; q < 4; q++) cf[nf][q] = 0.f;
            const __nv_bfloat16* arow = qw_s + (wi * 16 + arow_off) * 72 + acol_off;
            const __nv_bfloat16* brow = k_s + (wj * 32 + arow_off) * 72 + acol_off;
#pragma unroll
            for (int ks = 0; ks < 4; ks++) {
                uint32_t a4[4], b4[2][4];
                ldsm4b(a4, arow + ks * 16);
                ldsm4b(b4[0], brow + ks * 16);
                ldsm4b(b4[1], brow + 16 * 72 + ks * 16);
#pragma unroll
                for (int nf = 0; nf < 4; nf++) {
                    uint32_t bb[2] = { b4[nf >> 1][nf & 1], b4[nf >> 1][(nf & 1) + 2] };
                    mma_bf16(cf[nf], a4, bb);
                }
            }
            const int sr = wi * 16 + r;
#pragma unroll
            for (int nf = 0; nf < 4; nf++) {
                const int col = wj * 32 + nf * 8 + (cl << 1);
                *(float2*)&s_s[sr * 68 + col]       = make_float2(cf[nf][0], cf[nf][1]);
                *(float2*)&s_s[(sr + 8) * 68 + col] = make_float2(cf[nf][2], cf[nf][3]);
            }
        }
        // T(new block) = Qr Rks^T
        {
            float cf[4][4];
#pragma unroll
            for (int nf = 0; nf < 4; nf++)
#pragma unroll
                for (int q = 0; q < 4; q++) cf[nf][q] = 0.f;
            const __nv_bfloat16* arow = qr_s + (wi * 16 + arow_off) * 72 + acol_off;
            const __nv_bfloat16* brow = rk_s + (wj * 32 + arow_off) * 72 + acol_off;
#pragma unroll
            for (int ks = 0; ks < 4; ks++) {
                uint32_t a4[4], b4[2][4];
                ldsm4b(a4, arow + ks * 16);
                ldsm4b(b4[0], brow + ks * 16);
                ldsm4b(b4[1], brow + 16 * 72 + ks * 16);
#pragma unroll
                for (int nf = 0; nf < 4; nf++) {
                    uint32_t bb[2] = { b4[nf >> 1][nf & 1], b4[nf >> 1][(nf & 1) + 2] };
                    mma_bf16(cf[nf], a4, bb);
                }
            }
            const int sr = wi * 16 + r;
#pragma unroll
            for (int nf = 0; nf < 4; nf++) {
                const int col = ringoff + wj * 32 + nf * 8 + (cl << 1);
                *(float2*)&t_s[sr * 132 + col]       = make_float2(cf[nf][0], cf[nf][1]);
                *(float2*)&t_s[(sr + 8) * 132 + col] = make_float2(cf[nf][2], cf[nf][3]);
            }
        }
        __syncthreads();

        // softmax (thread: rows il = 4ty+a, cols 4tx..4tx+3); P -> bf16
#pragma unroll
        for (int a = 0; a < 4; a++) {
            const int il = (ty << 2) + a;
            const int gi = i0 + il;
            const float4 sv = *(const float4*)&s_s[il * 68 + (tx << 2)];
            float s4[4] = {sv.x, sv.y, sv.z, sv.w};
            float mx = -1e30f;
#pragma unroll
            for (int c = 0; c < 4; c++) {
                const int jl = (tx << 2) + c;
                const float tv = t_s[il * 132 + ((base + il - jl) & 127)];
                float v = (s4[c] + tv) * SCALEC;
                if (j0 + jl > gi) v = NEGC;
                s4[c] = v;
                mx = fmaxf(mx, v);
            }
#pragma unroll
            for (int off = 1; off < 16; off <<= 1)
                mx = fmaxf(mx, __shfl_xor_sync(0xffffffffu, mx, off, 16));
            const float mnew = fmaxf(m_r[a], mx);
            const float corr = __expf(m_r[a] - mnew);
            float psum = 0.f;
#pragma unroll
            for (int c = 0; c < 4; c++) {
                s4[c] = __expf(s4[c] - mnew);
                psum += s4[c];
            }
#pragma unroll
            for (int off = 1; off < 16; off <<= 1)
                psum += __shfl_xor_sync(0xffffffffu, psum, off, 16);
            l_r[a] = l_r[a] * corr + psum;
            m_r[a] = mnew;
            if (tx == 0) corr_s[il] = corr;
            __nv_bfloat162* pp = (__nv_bfloat162*)(p_s + il * 72 + (tx << 2));
            pp[0] = __floats2bfloat162_rn(s4[0], s4[1]);
            pp[1] = __floats2bfloat162_rn(s4[2], s4[3]);
        }
        __syncthreads();

        // PV: O += P V  (warp rows wi*16, cols(d) wj*32)
        {
            const float c0 = corr_s[wi * 16 + r], c1 = corr_s[wi * 16 + 8 + r];
#pragma unroll
            for (int nf = 0; nf < 4; nf++) {
                oacc[nf][0] *= c0; oacc[nf][1] *= c0;
                oacc[nf][2] *= c1; oacc[nf][3] *= c1;
            }
            const __nv_bfloat16* arow = p_s + (wi * 16 + arow_off) * 72 + acol_off;
            const __nv_bfloat16* brow = v_s + (wj * 32 + arow_off) * 72 + acol_off;
#pragma unroll
            for (int ks = 0; ks < 4; ks++) {
                uint32_t a4[4], b4[2][4];
                ldsm4b(a4, arow + ks * 16);
                ldsm4b(b4[0], brow + ks * 16);
                ldsm4b(b4[1], brow + 16 * 72 + ks * 16);
#pragma unroll
                for (int nf = 0; nf < 4; nf++) {
                    uint32_t bb[2] = { b4[nf >> 1][nf & 1], b4[nf >> 1][(nf & 1) + 2] };
                    mma_bf16(oacc[nf], a4, bb);
                }
            }
        }
    }

    if (tx == 0) {
#pragma unroll
        for (int a = 0; a < 4; a++) linv_s[(ty << 2) + a] = 1.f / l_r[a];
    }
    __syncthreads();
    {
        const int ir0 = i0 + wi * 16 + r;
        const float li0 = linv_s[wi * 16 + r], li1 = linv_s[wi * 16 + 8 + r];
#pragma unroll
        for (int nf = 0; nf < 4; nf++) {
            const int d = wj * 32 + nf * 8 + (cl << 1);
            *(__nv_bfloat162*)(attv + ((size_t)(ir0 * BSZC + b) * NHC + n) * DHC + d) =
                __floats2bfloat162_rn(oacc[nf][0] * li0, oacc[nf][1] * li0);
            *(__nv_bfloat162*)(attv + ((size_t)((ir0 + 8) * BSZC + b) * NHC + n) * DHC + d) =
                __floats2bfloat162_rn(oacc[nf][2] * li1, oacc[nf][3] * li1);
        }
    }
}

// ---------------- residual + LayerNorm ----------------
__global__ __launch_bounds__(256)
void ln_kernel(const float* __restrict__ w, const float* __restrict__ ao,
               const float* __restrict__ gamma, const float* __restrict__ beta,
               float* __restrict__ out)
{
    __shared__ float red[16];
    const int row = blockIdx.x, t = threadIdx.x;
    const size_t base = (size_t)row * DMC + t * 4;
    const float4 wv = *(const float4*)(w + base);
    const float4 av = *(const float4*)(ao + base);
    float x[4] = {wv.x + av.x, wv.y + av.y, wv.z + av.z, wv.w + av.w};
    float s1 = x[0] + x[1] + x[2] + x[3];
    float s2 = x[0]*x[0] + x[1]*x[1] + x[2]*x[2] + x[3]*x[3];
#pragma unroll
    for (int off = 16; off; off >>= 1) {
        s1 += __shfl_xor_sync(0xffffffffu, s1, off);
        s2 += __shfl_xor_sync(0xffffffffu, s2, off);
    }
    if ((t & 31) == 0) { red[t >> 5] = s1; red[8 + (t >> 5)] = s2; }
    __syncthreads();
    float ts1 = 0.f, ts2 = 0.f;
#pragma unroll
    for (int i = 0; i < 8; i++) { ts1 += red[i]; ts2 += red[8 + i]; }
    const float mu   = ts1 * (1.f / DMC);
    const float var  = ts2 * (1.f / DMC) - mu * mu;
    const float rstd = rsqrtf(var + 1e-5f);
    const float4 gv = *(const float4*)(gamma + t * 4);
    const float4 bv = *(const float4*)(beta + t * 4);
    float4 o;
    o.x = (x[0] - mu) * rstd * gv.x + bv.x;
    o.y = (x[1] - mu) * rstd * gv.y + bv.y;
    o.z = (x[2] - mu) * rstd * gv.z + bv.z;
    o.w = (x[3] - mu) * rstd * gv.w + bv.w;
    *(float4*)(out + base) = o;
}

// ---------------- launcher ----------------
extern "C" void kernel_launch(void* const* d_in, const int* in_sizes, int n_in,
                              void* d_out, int out_size)
{
    (void)in_sizes; (void)n_in; (void)out_size;
    const float* w    = (const float*)d_in[0];
    const float* r    = (const float*)d_in[1];
    const float* rwb  = (const float*)d_in[2];
    const float* rrb  = (const float*)d_in[3];
    const float* Wqkv = (const float*)d_in[4];
    const float* Wr   = (const float*)d_in[5];
    const float* Wo   = (const float*)d_in[6];
    const float* cwq  = (const float*)d_in[7];
    const float* cbq  = (const float*)d_in[8];
    const float* cwk  = (const float*)d_in[9];
    const float* cbk  = (const float*)d_in[10];
    const float* cwv  = (const float*)d_in[11];
    const float* cbv  = (const float*)d_in[12];
    const float* gam  = (const float*)d_in[13];
    const float* bet  = (const float*)d_in[14];

    __nv_bfloat16 *bheads, *bqh, *bkh, *bvh, *brk, *battv;
    __nv_bfloat16 *bw, *bqkv, *br, *bwr, *bwo, *wtq, *wtk, *wtv;
    float *aout;
    cudaGetSymbolAddress((void**)&bheads, g_bheads);
    cudaGetSymbolAddress((void**)&bqh,    g_bqh);
    cudaGetSymbolAddress((void**)&bkh,    g_bkh);
    cudaGetSymbolAddress((void**)&bvh,    g_bvh);
    cudaGetSymbolAddress((void**)&brk,    g_brk);
    cudaGetSymbolAddress((void**)&battv,  g_battv);
    cudaGetSymbolAddress((void**)&aout,   g_aout);
    cudaGetSymbolAddress((void**)&bw,     g_bw);
    cudaGetSymbolAddress((void**)&bqkv,   g_bqkv);
    cudaGetSymbolAddress((void**)&br,     g_br);
    cudaGetSymbolAddress((void**)&bwr,    g_bwr);
    cudaGetSymbolAddress((void**)&bwo,    g_bwo);
    cudaGetSymbolAddress((void**)&wtq,    g_wtq);
    cudaGetSymbolAddress((void**)&wtk,    g_wtk);
    cudaGetSymbolAddress((void**)&wtv,    g_wtv);

    cudaFuncSetAttribute(bgemm<true>,
                         cudaFuncAttributeMaxDynamicSharedMemorySize, BG_SMEM);
    cudaFuncSetAttribute(bgemm<false>,
                         cudaFuncAttributeMaxDynamicSharedMemorySize, BG_SMEM);
    cudaFuncSetAttribute(conv_mma,
                         cudaFuncAttributeMaxDynamicSharedMemorySize, CONV_SMEM);
    cudaFuncSetAttribute(attn_mma,
                         cudaFuncAttributeMaxDynamicSharedMemorySize, ATT_SMEM);

    // 0. converts + conv weight transforms
    cvt5<<<10240, 256>>>(w, Wqkv, r, Wr, Wo, bw, bqkv, br, bwr, bwo);
    wt_xform3<<<dim3(112, 3), 256>>>(cwq, cwk, cwv, wtq, wtk, wtv);
    // 1. heads = w @ W_qkv^T  -> bf16
    bgemm<true><<<dim3(H3C / 128, ROWSC / 128), 256, BG_SMEM>>>(
        bw, bqkv, bheads, ROWSC, H3C, DMC);
    // 2. r_head_k = r @ W_r^T -> bf16
    bgemm<true><<<dim3(DMC / 128, QLENC / 128), 256, BG_SMEM>>>(
        br, bwr, brk, QLENC, DMC, DMC);
    // 3. convs (bf16 tensor-core shifted GEMM, 3 fused)
    conv_mma<<<dim3(8, 64, 3), 256, CONV_SMEM>>>(bheads, wtq, wtk, wtv,
                                                 cbq, cbk, cbv, bqh, bkh, bvh);
    // 4. fused rel-attention, bf16 MMA, -> bf16
    attn_mma<<<dim3(16, 4, 16), 256, ATT_SMEM>>>(bqh, bkh, bvh, brk,
                                                 rwb, rrb, battv);
    // 5. out projection (fp32 out)
    bgemm<false><<<dim3(DMC / 128, ROWSC / 128), 256, BG_SMEM>>>(
        battv, bwo, aout, ROWSC, DMC, DMC);
    // 6. residual + LN
    ln_kernel<<<ROWSC, 256>>>(w, aout, gam, bet, (float*)d_out);
}

// round 6
// speedup vs baseline: 6.4409x; 1.0598x over previous
#include <cuda_runtime.h>
#include <cuda_bf16.h>
#include <cstdint>

#define QLENC 1024
#define BSZC  4
#define NHC   16
#define DHC   64
#define DMC   1024
#define H3C   3072
#define ROWSC 4096   // QLEN*BSZ
#define CONVC 7
#define SCALEC 0.125f
#define NEGC  -1e30f

// ---------------- scratch (no allocation allowed) ----------------
__device__ __nv_bfloat16 g_bheads[(size_t)ROWSC * H3C]; // [row][3*N*D]
__device__ __nv_bfloat16 g_bqh[(size_t)ROWSC * DMC];    // [l][b][n][d]
__device__ __nv_bfloat16 g_bkh[(size_t)ROWSC * DMC];
__device__ __nv_bfloat16 g_bvh[(size_t)ROWSC * DMC];
__device__ __nv_bfloat16 g_brk[(size_t)QLENC * DMC];    // [rho][n][d]
__device__ __nv_bfloat16 g_battv[(size_t)ROWSC * DMC];  // [row][n*64+d]
__device__ float g_aout[(size_t)ROWSC * DMC];
// bf16 operand copies
__device__ __nv_bfloat16 g_bw[(size_t)ROWSC * DMC];
__device__ __nv_bfloat16 g_bqkv[(size_t)H3C * DMC];
__device__ __nv_bfloat16 g_br[(size_t)QLENC * DMC];
__device__ __nv_bfloat16 g_bwr[(size_t)DMC * DMC];
__device__ __nv_bfloat16 g_bwo[(size_t)DMC * DMC];
// conv weights, [o][k*64+i] bf16
__device__ __nv_bfloat16 g_wtq[64 * 448];
__device__ __nv_bfloat16 g_wtk[64 * 448];
__device__ __nv_bfloat16 g_wtv[64 * 448];

// ---------------- helpers ----------------
__device__ __forceinline__ void mma_bf16(float c[4], const uint32_t a[4],
                                         const uint32_t b[2]) {
    asm volatile(
        "mma.sync.aligned.m16n8k16.row.col.f32.bf16.bf16.f32 "
        "{%0,%1,%2,%3}, {%4,%5,%6,%7}, {%8,%9}, {%0,%1,%2,%3};"
        : "+f"(c[0]), "+f"(c[1]), "+f"(c[2]), "+f"(c[3])
        : "r"(a[0]), "r"(a[1]), "r"(a[2]), "r"(a[3]), "r"(b[0]), "r"(b[1]));
}

__device__ __forceinline__ void ldsm4b(uint32_t d[4], const __nv_bfloat16* p) {
    uint32_t a = (uint32_t)__cvta_generic_to_shared(p);
    asm volatile("ldmatrix.sync.aligned.m8n8.x4.shared.b16 {%0,%1,%2,%3}, [%4];"
                 : "=r"(d[0]), "=r"(d[1]), "=r"(d[2]), "=r"(d[3]) : "r"(a));
}

__device__ __forceinline__ void cpa16(const void* s, const void* g) {
    uint32_t sa = (uint32_t)__cvta_generic_to_shared(s);
    asm volatile("cp.async.cg.shared.global [%0], [%1], 16;" :: "r"(sa), "l"(g));
}
#define CP_COMMIT() asm volatile("cp.async.commit_group;")
#define CP_WAIT2()  asm volatile("cp.async.wait_group 2;")

// ---------------- fp32 -> bf16 converts (fused) ----------------
__global__ __launch_bounds__(256)
void cvt5(const float* __restrict__ w, const float* __restrict__ Wqkv,
          const float* __restrict__ r, const float* __restrict__ Wr,
          const float* __restrict__ Wo,
          __nv_bfloat16* __restrict__ ow, __nv_bfloat16* __restrict__ oq,
          __nv_bfloat16* __restrict__ orr, __nv_bfloat16* __restrict__ owr,
          __nv_bfloat16* __restrict__ owo)
{
    int idx = blockIdx.x * 256 + threadIdx.x;   // float4 index
    const float* src; __nv_bfloat16* dst;
    if (idx < 1048576)      { src = w;    dst = ow; }
    else if (idx < 1835008) { src = Wqkv; dst = oq;  idx -= 1048576; }
    else if (idx < 2097152) { src = r;    dst = orr; idx -= 1835008; }
    else if (idx < 2359296) { src = Wr;   dst = owr; idx -= 2097152; }
    else                    { src = Wo;   dst = owo; idx -= 2359296; }
    const float4 v = *(const float4*)(src + (size_t)idx * 4);
    __nv_bfloat162* d2 = (__nv_bfloat162*)(dst + (size_t)idx * 4);
    d2[0] = __floats2bfloat162_rn(v.x, v.y);
    d2[1] = __floats2bfloat162_rn(v.z, v.w);
}

// ---------------- BF16 GEMM: C[M,N] = A[M,K] * B[N,K]^T -------------------
#define BG_SMEM (2 * 4 * 128 * 24 * 2)   // 49152 bytes
template<bool BOUT>
__global__ __launch_bounds__(256, 2)
void bgemm(const __nv_bfloat16* __restrict__ A, const __nv_bfloat16* __restrict__ B,
           void* __restrict__ Cv, int M, int N, int K)
{
    extern __shared__ __nv_bfloat16 shb[];
    __nv_bfloat16* As = shb;                 // [4][128][24]
    __nv_bfloat16* Bs = shb + 4 * 128 * 24;
    const int t = threadIdx.x, warp = t >> 5, lane = t & 31;
    const int r = lane >> 2, cl = lane & 3, g = lane >> 3, i_ = lane & 7;
    const int wm = (warp >> 2) * 64, wn = (warp & 3) * 32;
    const int m0 = blockIdx.y << 7, n0 = blockIdx.x << 7;
    const int srow = t >> 1, sc = (t & 1) << 3;

    const __nv_bfloat16* Ab = A + (size_t)(m0 + srow) * K + sc;
    const __nv_bfloat16* Bb = B + (size_t)(n0 + srow) * K + sc;
    __nv_bfloat16* Asw = As + srow * 24 + sc;
    __nv_bfloat16* Bsw = Bs + srow * 24 + sc;
    const int nk = K >> 4;

    float acc[4][4][4];
#pragma unroll
    for (int mf = 0; mf < 4; mf++)
#pragma unroll
        for (int nf = 0; nf < 4; nf++)
#pragma unroll
            for (int q = 0; q < 4; q++) acc[mf][nf][q] = 0.f;

#pragma unroll
    for (int s = 0; s < 3; s++) {
        cpa16(Asw + s * 3072, Ab + s * 16);
        cpa16(Bsw + s * 3072, Bb + s * 16);
        CP_COMMIT();
    }

    const int frag_off = (i_ + ((g & 1) << 3)) * 24 + ((g >> 1) << 3);

    for (int kt = 0; kt < nk; kt++) {
        CP_WAIT2();
        __syncthreads();
        if (kt + 3 < nk) {
            const int st = (kt + 3) & 3;
            cpa16(Asw + st * 3072, Ab + (kt + 3) * 16);
            cpa16(Bsw + st * 3072, Bb + (kt + 3) * 16);
            CP_COMMIT();
        }
        const __nv_bfloat16* Ac = As + (kt & 3) * 3072;
        const __nv_bfloat16* Bc = Bs + (kt & 3) * 3072;
        uint32_t af[4][4], bf[2][4];
#pragma unroll
        for (int mf = 0; mf < 4; mf++)
            ldsm4b(af[mf], Ac + (wm + mf * 16) * 24 + frag_off);
#pragma unroll
        for (int p = 0; p < 2; p++)
            ldsm4b(bf[p], Bc + (wn + p * 16) * 24 + frag_off);
#pragma unroll
        for (int mf = 0; mf < 4; mf++)
#pragma unroll
            for (int nf = 0; nf < 4; nf++) {
                uint32_t bb[2] = { bf[nf >> 1][nf & 1], bf[nf >> 1][(nf & 1) + 2] };
                mma_bf16(acc[mf][nf], af[mf], bb);
            }
    }

#pragma unroll
    for (int mf = 0; mf < 4; mf++) {
#pragma unroll
        for (int nf = 0; nf < 4; nf++) {
            const int row = m0 + wm + mf * 16 + r;
            const int col = n0 + wn + nf * 8 + (cl << 1);
            if (BOUT) {
                __nv_bfloat16* C = (__nv_bfloat16*)Cv;
                *(__nv_bfloat162*)(C + (size_t)row * N + col) =
                    __floats2bfloat162_rn(acc[mf][nf][0], acc[mf][nf][1]);
                *(__nv_bfloat162*)(C + (size_t)(row + 8) * N + col) =
                    __floats2bfloat162_rn(acc[mf][nf][2], acc[mf][nf][3]);
            } else {
                float* C = (float*)Cv;
                *(float2*)(C + (size_t)row * N + col) =
                    make_float2(acc[mf][nf][0], acc[mf][nf][1]);
                *(float2*)(C + (size_t)(row + 8) * N + col) =
                    make_float2(acc[mf][nf][2], acc[mf][nf][3]);
            }
        }
    }
}

// ---------------- conv weight transform (3 sets fused) ----------------
// cw[O][I][K] -> wt[o][k*64+i] bf16
__global__ void wt_xform3(const float* __restrict__ cwq, const float* __restrict__ cwk,
                          const float* __restrict__ cwv,
                          __nv_bfloat16* __restrict__ wtq, __nv_bfloat16* __restrict__ wtk,
                          __nv_bfloat16* __restrict__ wtv)
{
    const int idx = blockIdx.x * 256 + threadIdx.x;
    if (idx >= 64 * 448) return;
    const float* cw = (blockIdx.y == 0) ? cwq : (blockIdx.y == 1) ? cwk : cwv;
    __nv_bfloat16* wt = (blockIdx.y == 0) ? wtq : (blockIdx.y == 1) ? wtk : wtv;
    const int o = idx / 448, kidx = idx % 448;
    const int k = kidx >> 6, i = kidx & 63;
    wt[idx] = __float2bfloat16(cw[(o * 64 + i) * CONVC + k]);
}

// ---------------- conv1d as shifted GEMM, bf16, weights resident ----------
#define CONV_SMEM (134 * 72 * 2 + 64 * 456 * 2)
__global__ __launch_bounds__(256)
void conv_mma(const __nv_bfloat16* __restrict__ heads,
              const __nv_bfloat16* __restrict__ wtq, const __nv_bfloat16* __restrict__ wtk,
              const __nv_bfloat16* __restrict__ wtv,
              const float* __restrict__ cbq, const float* __restrict__ cbk,
              const float* __restrict__ cbv,
              __nv_bfloat16* __restrict__ oq, __nv_bfloat16* __restrict__ ok,
              __nv_bfloat16* __restrict__ ov)
{
    extern __shared__ __nv_bfloat16 shc[];
    __nv_bfloat16* xs = shc;              // [134][72]  (l+3, i)
    __nv_bfloat16* ws = shc + 134 * 72;   // [64][456]  (o, k*64+i)
    const int z = blockIdx.z;
    const int colbase = z * DMC;
    const __nv_bfloat16* wt = (z == 0) ? wtq : (z == 1) ? wtk : wtv;
    const float* cb = (z == 0) ? cbq : (z == 1) ? cbk : cbv;
    __nv_bfloat16* out = (z == 0) ? oq : (z == 1) ? ok : ov;

    const int t = threadIdx.x;
    const int warp = t >> 5, lane = t & 31;
    const int r = lane >> 2, cl = lane & 3, g = lane >> 3, i_ = lane & 7;
    const int wm = (warp >> 1) * 32, wn = (warp & 1) * 32;
    const int nb = blockIdx.y;
    const int n = nb >> 2, b = nb & 3;
    const int l0 = blockIdx.x << 7;

    for (int u = t; u < 134 * 8; u += 256) {
        const int row = u >> 3, i8 = (u & 7) << 3;
        const int gl = l0 + row - 3;
        uint4 v = make_uint4(0, 0, 0, 0);
        if (gl >= 0 && gl < QLENC)
            v = *(const uint4*)(heads + (size_t)(gl * BSZC + b) * H3C +
                                colbase + n * DHC + i8);
        *(uint4*)(xs + row * 72 + i8) = v;
    }
    for (int u = t; u < 64 * 56; u += 256) {
        const int o = u / 56, grp = u % 56;
        *(uint4*)(ws + o * 456 + grp * 8) = *(const uint4*)(wt + o * 448 + grp * 8);
    }
    __syncthreads();

    float acc[2][4][4];
#pragma unroll
    for (int mf = 0; mf < 2; mf++)
#pragma unroll
        for (int nf = 0; nf < 4; nf++)
#pragma unroll
            for (int q = 0; q < 4; q++) acc[mf][nf][q] = 0.f;

    const int arow_off = i_ + ((g & 1) << 3);
    const int acol_off = (g >> 1) << 3;

#pragma unroll 4
    for (int kc = 0; kc < 28; kc++) {
        const int k = kc >> 2;              // conv tap 0..6
        const int ibase = (kc & 3) << 4;    // i chunk base 0..48
        uint32_t af[2][4], bf[2][4];
#pragma unroll
        for (int mf = 0; mf < 2; mf++)
            ldsm4b(af[mf], xs + (wm + mf * 16 + k + arow_off) * 72 + ibase + acol_off);
#pragma unroll
        for (int p = 0; p < 2; p++)
            ldsm4b(bf[p], ws + (wn + p * 16 + arow_off) * 456 + kc * 16 + acol_off);
#pragma unroll
        for (int mf = 0; mf < 2; mf++)
#pragma unroll
            for (int nf = 0; nf < 4; nf++) {
                uint32_t bb[2] = { bf[nf >> 1][nf & 1], bf[nf >> 1][(nf & 1) + 2] };
                mma_bf16(acc[mf][nf], af[mf], bb);
            }
    }

#pragma unroll
    for (int mf = 0; mf < 2; mf++) {
#pragma unroll
        for (int nf = 0; nf < 4; nf++) {
            const int gl = l0 + wm + mf * 16 + r;
            const int o = wn + nf * 8 + (cl << 1);
            const float b0 = __ldg(cb + o), b1 = __ldg(cb + o + 1);
            *(__nv_bfloat162*)(out + (size_t)((gl * BSZC + b) * NHC + n) * DHC + o) =
                __floats2bfloat162_rn(acc[mf][nf][0] + b0, acc[mf][nf][1] + b1);
            *(__nv_bfloat162*)(out + (size_t)(((gl + 8) * BSZC + b) * NHC + n) * DHC + o) =
                __floats2bfloat162_rn(acc[mf][nf][2] + b0, acc[mf][nf][3] + b1);
        }
    }
}

// ---------------- fused rel-attention, bf16 MMA ----------------------------
// score[i,j] = scale*[(q_i+rwb)·k_j + (q_i+rrb)·rk[1023-(i-j)]]   (j<=i)
// SCALE folded into Q tiles. j-tiles DESCENDING; T ring over drel&127.
// Big i-tiles dispatched first (i0 = 15-bx) for load balance.
#define ATT_SMEM (6 * 64 * 72 * 2 + (64 * 68 + 64 * 132 + 128) * 4)
__global__ __launch_bounds__(256)
void attn_mma(const __nv_bfloat16* __restrict__ qh, const __nv_bfloat16* __restrict__ kh,
              const __nv_bfloat16* __restrict__ vh, const __nv_bfloat16* __restrict__ rk,
              const float* __restrict__ rwb, const float* __restrict__ rrb,
              __nv_bfloat16* __restrict__ attv)
{
    extern __shared__ char shraw[];
    __nv_bfloat16* qw_s = (__nv_bfloat16*)shraw;            // [64][72] (i,d)
    __nv_bfloat16* qr_s = qw_s + 64 * 72;
    __nv_bfloat16* k_s  = qr_s + 64 * 72;                   // [64][72] (j,d)
    __nv_bfloat16* v_s  = k_s  + 64 * 72;                   // [64][72] (d,j)
    __nv_bfloat16* rk_s = v_s  + 64 * 72;                   // [64][72] (x,d)
    __nv_bfloat16* p_s  = rk_s + 64 * 72;                   // [64][72] (i,j)
    float* s_s    = (float*)(p_s + 64 * 72);                // [64][68]
    float* t_s    = s_s + 64 * 68;                          // [64][132] ring
    float* corr_s = t_s + 64 * 132;                         // [64]
    float* linv_s = corr_s + 64;                            // [64]

    const int i0 = (15 - blockIdx.x) << 6;  // big tiles first
    const int b = blockIdx.y, n = blockIdx.z;
    const int t = threadIdx.x, warp = t >> 5, lane = t & 31;
    const int r = lane >> 2, cl = lane & 3, g = lane >> 3, i_ = lane & 7;
    const int wi = warp >> 1, wj = warp & 1;
    const int ty = t >> 4, tx = t & 15;

    // Q tiles with biases, pre-scaled by SCALEC
    for (int u = t; u < 512; u += 256) {
        const int il = u >> 3, d8 = (u & 7) << 3;
        const uint4 qv = *(const uint4*)(qh +
            ((size_t)((i0 + il) * BSZC + b) * NHC + n) * DHC + d8);
        const __nv_bfloat162* q2 = (const __nv_bfloat162*)&qv;
        const float4 wv0 = *(const float4*)(rwb + n * DHC + d8);
        const float4 wv1 = *(const float4*)(rwb + n * DHC + d8 + 4);
        const float4 rv0 = *(const float4*)(rrb + n * DHC + d8);
        const float4 rv1 = *(const float4*)(rrb + n * DHC + d8 + 4);
        float qf[8];
#pragma unroll
        for (int q = 0; q < 4; q++) {
            float2 f = __bfloat1622float2(q2[q]);
            qf[2 * q] = f.x; qf[2 * q + 1] = f.y;
        }
        __nv_bfloat162* dw = (__nv_bfloat162*)(qw_s + il * 72 + d8);
        __nv_bfloat162* dr = (__nv_bfloat162*)(qr_s + il * 72 + d8);
        dw[0] = __floats2bfloat162_rn((qf[0] + wv0.x) * SCALEC, (qf[1] + wv0.y) * SCALEC);
        dw[1] = __floats2bfloat162_rn((qf[2] + wv0.z) * SCALEC, (qf[3] + wv0.w) * SCALEC);
        dw[2] = __floats2bfloat162_rn((qf[4] + wv1.x) * SCALEC, (qf[5] + wv1.y) * SCALEC);
        dw[3] = __floats2bfloat162_rn((qf[6] + wv1.z) * SCALEC, (qf[7] + wv1.w) * SCALEC);
        dr[0] = __floats2bfloat162_rn((qf[0] + rv0.x) * SCALEC, (qf[1] + rv0.y) * SCALEC);
        dr[1] = __floats2bfloat162_rn((qf[2] + rv0.z) * SCALEC, (qf[3] + rv0.w) * SCALEC);
        dr[2] = __floats2bfloat162_rn((qf[4] + rv1.x) * SCALEC, (qf[5] + rv1.y) * SCALEC);
        dr[3] = __floats2bfloat162_rn((qf[6] + rv1.z) * SCALEC, (qf[7] + rv1.w) * SCALEC);
    }

    float oacc[4][4];
#pragma unroll
    for (int nf = 0; nf < 4; nf++)
#pragma unroll
        for (int q = 0; q < 4; q++) oacc[nf][q] = 0.f;
    float m_r[4], l_r[4];
#pragma unroll
    for (int a = 0; a < 4; a++) { m_r[a] = -1e30f; l_r[a] = 0.f; }

    const int arow_off = i_ + ((g & 1) << 3);
    const int acol_off = (g >> 1) << 3;

    for (int j0 = i0; j0 >= 0; j0 -= 64) {
        const int base = i0 - j0;
        const int ringoff = base & 127;
        __syncthreads();
        // K, V(transposed), rk
        for (int u = t; u < 512; u += 256) {
            const int jl = u >> 3, d8 = (u & 7) << 3;
            const size_t gi = ((size_t)((j0 + jl) * BSZC + b) * NHC + n) * DHC + d8;
            *(uint4*)(k_s + jl * 72 + d8) = *(const uint4*)(kh + gi);
            const uint4 vv = *(const uint4*)(vh + gi);
            const __nv_bfloat16* v8 = (const __nv_bfloat16*)&vv;
#pragma unroll
            for (int q = 0; q < 8; q++)
                v_s[(d8 + q) * 72 + jl] = v8[q];
            const int drel = base + jl;
            *(uint4*)(rk_s + jl * 72 + d8) =
                *(const uint4*)(rk + (size_t)(QLENC - 1 - drel) * DMC + n * DHC + d8);
        }
        __syncthreads();

        // S = Qw K^T
        {
            float cf[4][4];
#pragma unroll
            for (int nf = 0; nf < 4; nf++)
#pragma unroll
                for (int q = 0; q < 4; q++) cf[nf][q] = 0.f;
            const __nv_bfloat16* arow = qw_s + (wi * 16 + arow_off) * 72 + acol_off;
            const __nv_bfloat16* brow = k_s + (wj * 32 + arow_off) * 72 + acol_off;
#pragma unroll
            for (int ks = 0; ks < 4; ks++) {
                uint32_t a4[4], b4[2][4];
                ldsm4b(a4, arow + ks * 16);
                ldsm4b(b4[0], brow + ks * 16);
                ldsm4b(b4[1], brow + 16 * 72 + ks * 16);
#pragma unroll
                for (int nf = 0; nf < 4; nf++) {
                    uint32_t bb[2] = { b4[nf >> 1][nf & 1], b4[nf >> 1][(nf & 1) + 2] };
                    mma_bf16(cf[nf], a4, bb);
                }
            }
            const int sr = wi * 16 + r;
#pragma unroll
            for (int nf = 0; nf < 4; nf++) {
                const int col = wj * 32 + nf * 8 + (cl << 1);
                *(float2*)&s_s[sr * 68 + col]       = make_float2(cf[nf][0], cf[nf][1]);
                *(float2*)&s_s[(sr + 8) * 68 + col] = make_float2(cf[nf][2], cf[nf][3]);
            }
        }
        // T(new block) = Qr Rks^T
        {
            float cf[4][4];
#pragma unroll
            for (int nf = 0; nf < 4; nf++)
#pragma unroll
                for (int q = 0; q < 4; q++) cf[nf][q] = 0.f;
            const __nv_bfloat16* arow = qr_s + (wi * 16 + arow_off) * 72 + acol_off;
            const __nv_bfloat16* brow = rk_s + (wj * 32 + arow_off) * 72 + acol_off;
#pragma unroll
            for (int ks = 0; ks < 4; ks++) {
                uint32_t a4[4], b4[2][4];
                ldsm4b(a4, arow + ks * 16);
                ldsm4b(b4[0], brow + ks * 16);
                ldsm4b(b4[1], brow + 16 * 72 + ks * 16);
#pragma unroll
                for (int nf = 0; nf < 4; nf++) {
                    uint32_t bb[2] = { b4[nf >> 1][nf & 1], b4[nf >> 1][(nf & 1) + 2] };
                    mma_bf16(cf[nf], a4, bb);
                }
            }
            const int sr = wi * 16 + r;
#pragma unroll
            for (int nf = 0; nf < 4; nf++) {
                const int col = ringoff + wj * 32 + nf * 8 + (cl << 1);
                *(float2*)&t_s[sr * 132 + col]       = make_float2(cf[nf][0], cf[nf][1]);
                *(float2*)&t_s[(sr + 8) * 132 + col] = make_float2(cf[nf][2], cf[nf][3]);
            }
        }
        __syncthreads();

        // softmax; P -> bf16
#pragma unroll
        for (int a = 0; a < 4; a++) {
            const int il = (ty << 2) + a;
            const int gi = i0 + il;
            const float4 sv = *(const float4*)&s_s[il * 68 + (tx << 2)];
            float s4[4] = {sv.x, sv.y, sv.z, sv.w};
            float mx = -1e30f;
#pragma unroll
            for (int c = 0; c < 4; c++) {
                const int jl = (tx << 2) + c;
                const float tv = t_s[il * 132 + ((base + il - jl) & 127)];
                float v = s4[c] + tv;
                if (j0 + jl > gi) v = NEGC;
                s4[c] = v;
                mx = fmaxf(mx, v);
            }
#pragma unroll
            for (int off = 1; off < 16; off <<= 1)
                mx = fmaxf(mx, __shfl_xor_sync(0xffffffffu, mx, off, 16));
            const float mnew = fmaxf(m_r[a], mx);
            const float corr = __expf(m_r[a] - mnew);
            float psum = 0.f;
#pragma unroll
            for (int c = 0; c < 4; c++) {
                s4[c] = __expf(s4[c] - mnew);
                psum += s4[c];
            }
#pragma unroll
            for (int off = 1; off < 16; off <<= 1)
                psum += __shfl_xor_sync(0xffffffffu, psum, off, 16);
            l_r[a] = l_r[a] * corr + psum;
            m_r[a] = mnew;
            if (tx == 0) corr_s[il] = corr;
            __nv_bfloat162* pp = (__nv_bfloat162*)(p_s + il * 72 + (tx << 2));
            pp[0] = __floats2bfloat162_rn(s4[0], s4[1]);
            pp[1] = __floats2bfloat162_rn(s4[2], s4[3]);
        }
        __syncthreads();

        // PV: O += P V
        {
            const float c0 = corr_s[wi * 16 + r], c1 = corr_s[wi * 16 + 8 + r];
#pragma unroll
            for (int nf = 0; nf < 4; nf++) {
                oacc[nf][0] *= c0; oacc[nf][1] *= c0;
                oacc[nf][2] *= c1; oacc[nf][3] *= c1;
            }
            const __nv_bfloat16* arow = p_s + (wi * 16 + arow_off) * 72 + acol_off;
            const __nv_bfloat16* brow = v_s + (wj * 32 + arow_off) * 72 + acol_off;
#pragma unroll
            for (int ks = 0; ks < 4; ks++) {
                uint32_t a4[4], b4[2][4];
                ldsm4b(a4, arow + ks * 16);
                ldsm4b(b4[0], brow + ks * 16);
                ldsm4b(b4[1], brow + 16 * 72 + ks * 16);
#pragma unroll
                for (int nf = 0; nf < 4; nf++) {
                    uint32_t bb[2] = { b4[nf >> 1][nf & 1], b4[nf >> 1][(nf & 1) + 2] };
                    mma_bf16(oacc[nf], a4, bb);
                }
            }
        }
    }

    if (tx == 0) {
#pragma unroll
        for (int a = 0; a < 4; a++) linv_s[(ty << 2) + a] = 1.f / l_r[a];
    }
    __syncthreads();
    {
        const int ir0 = i0 + wi * 16 + r;
        const float li0 = linv_s[wi * 16 + r], li1 = linv_s[wi * 16 + 8 + r];
#pragma unroll
        for (int nf = 0; nf < 4; nf++) {
            const int d = wj * 32 + nf * 8 + (cl << 1);
            *(__nv_bfloat162*)(attv + ((size_t)(ir0 * BSZC + b) * NHC + n) * DHC + d) =
                __floats2bfloat162_rn(oacc[nf][0] * li0, oacc[nf][1] * li0);
            *(__nv_bfloat162*)(attv + ((size_t)((ir0 + 8) * BSZC + b) * NHC + n) * DHC + d) =
                __floats2bfloat162_rn(oacc[nf][2] * li1, oacc[nf][3] * li1);
        }
    }
}

// ---------------- residual + LayerNorm ----------------
__global__ __launch_bounds__(256)
void ln_kernel(const float* __restrict__ w, const float* __restrict__ ao,
               const float* __restrict__ gamma, const float* __restrict__ beta,
               float* __restrict__ out)
{
    __shared__ float red[16];
    const int row = blockIdx.x, t = threadIdx.x;
    const size_t base = (size_t)row * DMC + t * 4;
    const float4 wv = *(const float4*)(w + base);
    const float4 av = *(const float4*)(ao + base);
    float x[4] = {wv.x + av.x, wv.y + av.y, wv.z + av.z, wv.w + av.w};
    float s1 = x[0] + x[1] + x[2] + x[3];
    float s2 = x[0]*x[0] + x[1]*x[1] + x[2]*x[2] + x[3]*x[3];
#pragma unroll
    for (int off = 16; off; off >>= 1) {
        s1 += __shfl_xor_sync(0xffffffffu, s1, off);
        s2 += __shfl_xor_sync(0xffffffffu, s2, off);
    }
    if ((t & 31) == 0) { red[t >> 5] = s1; red[8 + (t >> 5)] = s2; }
    __syncthreads();
    float ts1 = 0.f, ts2 = 0.f;
#pragma unroll
    for (int i = 0; i < 8; i++) { ts1 += red[i]; ts2 += red[8 + i]; }
    const float mu   = ts1 * (1.f / DMC);
    const float var  = ts2 * (1.f / DMC) - mu * mu;
    const float rstd = rsqrtf(var + 1e-5f);
    const float4 gv = *(const float4*)(gamma + t * 4);
    const float4 bv = *(const float4*)(beta + t * 4);
    float4 o;
    o.x = (x[0] - mu) * rstd * gv.x + bv.x;
    o.y = (x[1] - mu) * rstd * gv.y + bv.y;
    o.z = (x[2] - mu) * rstd * gv.z + bv.z;
    o.w = (x[3] - mu) * rstd * gv.w + bv.w;
    *(float4*)(out + base) = o;
}

// ---------------- launcher ----------------
extern "C" void kernel_launch(void* const* d_in, const int* in_sizes, int n_in,
                              void* d_out, int out_size)
{
    (void)in_sizes; (void)n_in; (void)out_size;
    const float* w    = (const float*)d_in[0];
    const float* r    = (const float*)d_in[1];
    const float* rwb  = (const float*)d_in[2];
    const float* rrb  = (const float*)d_in[3];
    const float* Wqkv = (const float*)d_in[4];
    const float* Wr   = (const float*)d_in[5];
    const float* Wo   = (const float*)d_in[6];
    const float* cwq  = (const float*)d_in[7];
    const float* cbq  = (const float*)d_in[8];
    const float* cwk  = (const float*)d_in[9];
    const float* cbk  = (const float*)d_in[10];
    const float* cwv  = (const float*)d_in[11];
    const float* cbv  = (const float*)d_in[12];
    const float* gam  = (const float*)d_in[13];
    const float* bet  = (const float*)d_in[14];

    __nv_bfloat16 *bheads, *bqh, *bkh, *bvh, *brk, *battv;
    __nv_bfloat16 *bw, *bqkv, *br, *bwr, *bwo, *wtq, *wtk, *wtv;
    float *aout;
    cudaGetSymbolAddress((void**)&bheads, g_bheads);
    cudaGetSymbolAddress((void**)&bqh,    g_bqh);
    cudaGetSymbolAddress((void**)&bkh,    g_bkh);
    cudaGetSymbolAddress((void**)&bvh,    g_bvh);
    cudaGetSymbolAddress((void**)&brk,    g_brk);
    cudaGetSymbolAddress((void**)&battv,  g_battv);
    cudaGetSymbolAddress((void**)&aout,   g_aout);
    cudaGetSymbolAddress((void**)&bw,     g_bw);
    cudaGetSymbolAddress((void**)&bqkv,   g_bqkv);
    cudaGetSymbolAddress((void**)&br,     g_br);
    cudaGetSymbolAddress((void**)&bwr,    g_bwr);
    cudaGetSymbolAddress((void**)&bwo,    g_bwo);
    cudaGetSymbolAddress((void**)&wtq,    g_wtq);
    cudaGetSymbolAddress((void**)&wtk,    g_wtk);
    cudaGetSymbolAddress((void**)&wtv,    g_wtv);

    cudaFuncSetAttribute(bgemm<true>,
                         cudaFuncAttributeMaxDynamicSharedMemorySize, BG_SMEM);
    cudaFuncSetAttribute(bgemm<false>,
                         cudaFuncAttributeMaxDynamicSharedMemorySize, BG_SMEM);
    cudaFuncSetAttribute(conv_mma,
                         cudaFuncAttributeMaxDynamicSharedMemorySize, CONV_SMEM);
    cudaFuncSetAttribute(attn_mma,
                         cudaFuncAttributeMaxDynamicSharedMemorySize, ATT_SMEM);

    // fork side stream for wt_xform3 + gemm2 (both off the critical path).
    // Host-side objects only; created during capture call, never freed
    // (kernel_launch is invoked only a handful of times).
    cudaStream_t sB;
    cudaEvent_t eFork, eCvt, eWt, eG2;
    cudaStreamCreateWithFlags(&sB, cudaStreamNonBlocking);
    cudaEventCreateWithFlags(&eFork, cudaEventDisableTiming);
    cudaEventCreateWithFlags(&eCvt,  cudaEventDisableTiming);
    cudaEventCreateWithFlags(&eWt,   cudaEventDisableTiming);
    cudaEventCreateWithFlags(&eG2,   cudaEventDisableTiming);

    cudaEventRecord(eFork, 0);
    cudaStreamWaitEvent(sB, eFork, 0);

    // side stream: conv weight transform, then (after cvt5) gemm2
    wt_xform3<<<dim3(112, 3), 256, 0, sB>>>(cwq, cwk, cwv, wtq, wtk, wtv);
    cudaEventRecord(eWt, sB);

    // main stream: converts + big gemm
    cvt5<<<10240, 256>>>(w, Wqkv, r, Wr, Wo, bw, bqkv, br, bwr, bwo);
    cudaEventRecord(eCvt, 0);
    bgemm<true><<<dim3(H3C / 128, ROWSC / 128), 256, BG_SMEM>>>(
        bw, bqkv, bheads, ROWSC, H3C, DMC);

    // side stream: r_head_k = r @ W_r^T (overlaps gemm1)
    cudaStreamWaitEvent(sB, eCvt, 0);
    bgemm<true><<<dim3(DMC / 128, QLENC / 128), 256, BG_SMEM, sB>>>(
        br, bwr, brk, QLENC, DMC, DMC);
    cudaEventRecord(eG2, sB);

    // main stream: convs need gemm1 (in-stream) + wt_xform3 (side)
    cudaStreamWaitEvent(0, eWt, 0);
    conv_mma<<<dim3(8, 64, 3), 256, CONV_SMEM>>>(bheads, wtq, wtk, wtv,
                                                 cbq, cbk, cbv, bqh, bkh, bvh);
    // attention needs convs (in-stream) + gemm2 (side) -- join
    cudaStreamWaitEvent(0, eG2, 0);
    attn_mma<<<dim3(16, 4, 16), 256, ATT_SMEM>>>(bqh, bkh, bvh, brk,
                                                 rwb, rrb, battv);
    // out projection + residual/LN
    bgemm<false><<<dim3(DMC / 128, ROWSC / 128), 256, BG_SMEM>>>(
        battv, bwo, aout, ROWSC, DMC, DMC);
    ln_kernel<<<ROWSC, 256>>>(w, aout, gam, bet, (float*)d_out);
}